// round 1
// baseline (speedup 1.0000x reference)
#include <cuda_runtime.h>
#include <math.h>

// Problem-size capacities (dataset is fixed: N=4000, E=64000, C=64)
#define NMAX 4000
#define EMAX 64000
#define CHAN 64
#define NB 8
#define CSZ 64          // edges per sort chunk
#define CHMAX ((EMAX + CSZ - 1) / CSZ)   // 1000
#define NK 13           // components: rank0(1) + rank1(3) + rank2(9)

// ---------------- scratch (static device globals; no allocation) -------------
__device__ float g_ef[EMAX * NB];            // radial basis per edge
__device__ float g_Y[EMAX * NK];             // cartesian harmonics ranks 0..2
__device__ float g_z[(size_t)EMAX * 192];    // per-edge per-rank per-channel messages (pre-Y)
__device__ float g_A[NMAX * CHAN * NK];      // node features A[n][c][k]
__device__ float g_h0a[NMAX * CHAN];
__device__ float g_h0b[NMAX * CHAN];
__device__ float g_h1[NMAX * CHAN * 3];
__device__ float g_h2[NMAX * CHAN * 9];
__device__ float g_s[NMAX * CHAN];           // gate scalars
__device__ int   g_hist[CHMAX * NMAX];       // chunked histogram (16 MB)
__device__ int   g_rank[EMAX];               // rank within (chunk, dst)
__device__ int   g_cnt[NMAX];
__device__ int   g_off[NMAX + 1];
__device__ int   g_perm[EMAX];               // edges sorted by dst (stable, deterministic)

// ---------------- utility kernels -------------------------------------------
__global__ void k_zero(int total) {
    int stride = gridDim.x * blockDim.x;
    for (int i = blockIdx.x * blockDim.x + threadIdx.x; i < total; i += stride) {
        if (i < CHMAX * NMAX) g_hist[i] = 0;
        else g_cnt[i - CHMAX * NMAX] = 0;
    }
}

// geometry: r, u, bessel * cutoff, harmonics Y0..Y2
__global__ void k_geom(const float* __restrict__ ev, int E) {
    int e = blockIdx.x * blockDim.x + threadIdx.x;
    if (e >= E) return;
    float vx = ev[3 * e], vy = ev[3 * e + 1], vz = ev[3 * e + 2];
    float r = sqrtf(vx * vx + vy * vy + vz * vz);
    float inv = 1.f / r;
    float ux = vx * inv, uy = vy * inv, uz = vz * inv;
    float x = r * (1.f / 6.f);
    float fc = 0.f;
    if (x < 1.f) {
        float x2 = x * x;
        float x5 = x2 * x2 * x;
        fc = 1.f - 21.f * x5 + 35.f * x5 * x - 15.f * x5 * x2;
    }
    float pref = sqrtf(2.f / 6.f) * inv * fc;
    const float PI = 3.14159265358979323846f;
    float arg = PI * r * (1.f / 6.f);
#pragma unroll
    for (int n = 0; n < NB; n++) {
        g_ef[e * NB + n] = pref * sinf((float)(n + 1) * arg);
    }
    float* Y = g_Y + e * NK;
    Y[0] = 1.f;
    Y[1] = ux; Y[2] = uy; Y[3] = uz;
    Y[4] = ux * ux; Y[5] = ux * uy; Y[6] = ux * uz;
    Y[7] = uy * ux; Y[8] = uy * uy; Y[9] = uy * uz;
    Y[10] = uz * ux; Y[11] = uz * uy; Y[12] = uz * uz;
}

// h0 = W_emb[species]
__global__ void k_h0init(const int* __restrict__ spec, const float* __restrict__ Wemb, int N) {
    int i = blockIdx.x * blockDim.x + threadIdx.x;
    if (i >= N * CHAN) return;
    int n = i >> 6, c = i & 63;
    g_h0a[i] = Wemb[spec[n] * CHAN + c];
}

// ---------------- deterministic counting sort of edges by dst ----------------
__global__ void k_chunk(const int* __restrict__ eidx, int E, int N, int CH) {
    int j = blockIdx.x * blockDim.x + threadIdx.x;
    if (j >= CH) return;
    int base = j * CSZ;
    int end = min(E, base + CSZ);
    int* hrow = g_hist + j * N;
    for (int e = base; e < end; e++) {
        int d = eidx[E + e];
        int r = hrow[d];
        g_rank[e] = r;
        hrow[d] = r + 1;
    }
}

__global__ void k_count(int N, int CH) {
    int n = blockIdx.x * blockDim.x + threadIdx.x;
    if (n >= N) return;
    int s = 0;
    for (int j = 0; j < CH; j++) s += g_hist[j * N + n];
    g_cnt[n] = s;
}

__global__ void k_scan(int N) {
    __shared__ int sh[1024];
    __shared__ int carry_s;
    int t = threadIdx.x;
    if (t == 0) carry_s = 0;
    __syncthreads();
    int ntile = (N + 1023) / 1024;
    for (int tile = 0; tile < ntile; tile++) {
        int i = tile * 1024 + t;
        int v = (i < N) ? g_cnt[i] : 0;
        sh[t] = v;
        __syncthreads();
        for (int o = 1; o < 1024; o <<= 1) {
            int add = (t >= o) ? sh[t - o] : 0;
            __syncthreads();
            sh[t] += add;
            __syncthreads();
        }
        int incl = sh[t];
        int carry = carry_s;
        if (i < N) g_off[i] = carry + incl - v;
        if (i == N - 1) g_off[N] = carry + incl;
        __syncthreads();
        if (t == 1023) carry_s = carry + incl;
        __syncthreads();
    }
}

__global__ void k_colpre(int N, int CH) {
    int n = blockIdx.x * blockDim.x + threadIdx.x;
    if (n >= N) return;
    int cum = g_off[n];
    for (int j = 0; j < CH; j++) {
        int t = g_hist[j * N + n];
        g_hist[j * N + n] = cum;
        cum += t;
    }
}

__global__ void k_scatter(const int* __restrict__ eidx, int E, int N) {
    int e = blockIdx.x * blockDim.x + threadIdx.x;
    if (e >= E) return;
    int j = e / CSZ;
    int d = eidx[E + e];
    int pos = g_hist[j * N + d] + g_rank[e];
    g_perm[pos] = e;
}

// ---------------- per-layer kernels ------------------------------------------
// s = h0 @ W_gate[layer]
__global__ void k_gate(const float* __restrict__ Wg, int layer) {
    __shared__ float sh0[CHAN];
    int n = blockIdx.x;
    int c = threadIdx.x;
    const float* h0 = (layer == 0) ? g_h0a : g_h0b;
    sh0[c] = h0[n * CHAN + c];
    __syncthreads();
    const float* W = Wg + layer * CHAN * CHAN;
    float acc = 0.f;
#pragma unroll 8
    for (int d = 0; d < CHAN; d++) acc += sh0[d] * W[d * CHAN + c];
    g_s[n * CHAN + c] = acc;
}

// per-edge: hidden = silu(ef@W1); s_e (gate + density trick); z = (hidden@W2)*s_e
// block = 32 edges, 256 threads. Phase3: 192 threads, each owns one output column
// (L,c) and 32 edge-accumulators.
__global__ void k_edge(const float* __restrict__ rw1, const float* __restrict__ rw2,
                       const int* __restrict__ eidx, int E, int layer) {
    __shared__ float shH[64][32];   // hidden transposed [j][edge]
    __shared__ float shS[32][65];   // s_e [edge][c], padded
    int e0 = blockIdx.x * 32;
    int tid = threadIdx.x;
    const float* W1 = rw1 + layer * NB * CHAN;

    // phases 1+2: hidden + s_e for 32 edges x 64 channels (8 per thread)
#pragma unroll
    for (int it = 0; it < 8; it++) {
        int idx = it * 256 + tid;
        int el = idx & 31;
        int c = idx >> 5;
        int e = e0 + el;
        const float* ef = g_ef + e * NB;
        float h = 0.f;
#pragma unroll
        for (int i = 0; i < NB; i++) h += ef[i] * W1[i * CHAN + c];
        h = h * (1.f / (1.f + __expf(-h)));   // silu
        shH[c][el] = h;

        int src = eidx[e];
        float se = g_s[src * CHAN + c];
        if (layer > 0) {
            const float* y = g_Y + e * NK;
            const float* h1 = g_h1 + src * CHAN * 3 + c * 3;
            se += h1[0] * y[1] + h1[1] * y[2] + h1[2] * y[3];
            const float* h2 = g_h2 + src * CHAN * 9 + c * 9;
#pragma unroll
            for (int j = 0; j < 9; j++) se += h2[j] * y[4 + j];
        }
        shS[el][c] = se;
    }
    __syncthreads();

    // phase 3: z[e][L][c] = (sum_j hidden[e][j] * W2[j][L*64+c]) * s_e[e][c]
    if (tid < 192) {
        int L = tid >> 6, c = tid & 63;
        const float* w2p = rw2 + layer * CHAN * 256 + L * CHAN + c;
        float acc[32];
#pragma unroll
        for (int q = 0; q < 32; q++) acc[q] = 0.f;
#pragma unroll 4
        for (int j = 0; j < 64; j++) {
            float w = w2p[j * 256];
            const float4* hp = reinterpret_cast<const float4*>(shH[j]);
#pragma unroll
            for (int q = 0; q < 8; q++) {
                float4 v = hp[q];
                acc[4 * q + 0] += v.x * w;
                acc[4 * q + 1] += v.y * w;
                acc[4 * q + 2] += v.z * w;
                acc[4 * q + 3] += v.w * w;
            }
        }
        float* zp = g_z + (size_t)e0 * 192 + L * CHAN + c;
#pragma unroll
        for (int el = 0; el < 32; el++) {
            zp[(size_t)el * 192] = acc[el] * shS[el][c];
        }
    }
}

// gather: warp per node; accumulate A[n][c][k] = sum_e z[e][L(k)][c]*Y[e][k] / AVG
__global__ void k_gather(int N) {
    int warp = threadIdx.x >> 5;
    int lane = threadIdx.x & 31;
    int node = blockIdx.x * 4 + warp;
    if (node >= N) return;
    float a0[NK], a1[NK];
#pragma unroll
    for (int k = 0; k < NK; k++) { a0[k] = 0.f; a1[k] = 0.f; }
    int beg = g_off[node], end = g_off[node + 1];
    for (int i = beg; i < end; i++) {
        int e = g_perm[i];
        const float* zp = g_z + (size_t)e * 192;
        float z0a = zp[lane],       z0b = zp[32 + lane];
        float z1a = zp[64 + lane],  z1b = zp[96 + lane];
        float z2a = zp[128 + lane], z2b = zp[160 + lane];
        const float* y = g_Y + e * NK;
        a0[0] += z0a; a1[0] += z0b;
#pragma unroll
        for (int k = 1; k < 4; k++) {
            float yv = y[k];
            a0[k] += z1a * yv; a1[k] += z1b * yv;
        }
#pragma unroll
        for (int k = 4; k < NK; k++) {
            float yv = y[k];
            a0[k] += z2a * yv; a1[k] += z2b * yv;
        }
    }
    const float inv = 1.f / 16.f;
    float* Ap = g_A + node * CHAN * NK;
#pragma unroll
    for (int k = 0; k < NK; k++) {
        Ap[lane * NK + k] = a0[k] * inv;
        Ap[(lane + 32) * NK + k] = a1[k] * inv;
    }
}

// self-contraction + output
__global__ void k_update(const float* __restrict__ Wmix, const float* __restrict__ Wsc,
                         const int* __restrict__ spec, float* __restrict__ out,
                         int layer, int N) {
    __shared__ float sA[CHAN * NK];
    int n = blockIdx.x;
    int d = threadIdx.x;
    for (int i = d; i < CHAN * NK; i += CHAN) sA[i] = g_A[n * CHAN * NK + i];
    __syncthreads();

    const float* h0in = (layer == 0) ? g_h0a : g_h0b;
    float* h0out = (layer == 0) ? g_h0b : g_h0a;

    float A0d = sA[d * NK];
    float A1d[3], A2d[9];
#pragma unroll
    for (int k = 0; k < 3; k++) A1d[k] = sA[d * NK + 1 + k];
#pragma unroll
    for (int k = 0; k < 9; k++) A2d[k] = sA[d * NK + 4 + k];

    const float* Wm = Wmix + layer * 3 * CHAN * CHAN;
    float mat0 = 0.f;
    float mat1[3] = {0.f, 0.f, 0.f};
    float mat2[9] = {0.f, 0.f, 0.f, 0.f, 0.f, 0.f, 0.f, 0.f, 0.f};
    for (int c = 0; c < CHAN; c++) {
        mat0 += sA[c * NK] * Wm[c * CHAN + d];
        if (layer == 0) {
            float w1m = Wm[CHAN * CHAN + c * CHAN + d];
#pragma unroll
            for (int k = 0; k < 3; k++) mat1[k] += sA[c * NK + 1 + k] * w1m;
            float w2m = Wm[2 * CHAN * CHAN + c * CHAN + d];
#pragma unroll
            for (int k = 0; k < 9; k++) mat2[k] += sA[c * NK + 4 + k] * w2m;
        }
    }
    float sq = 0.f;
#pragma unroll
    for (int k = 0; k < 3; k++) sq += A1d[k] * A1d[k];
#pragma unroll
    for (int k = 0; k < 9; k++) sq += A2d[k] * A2d[k];

    int sp = spec[n];
    float sc0 = Wsc[layer * 10 * CHAN + sp * CHAN + d] * h0in[n * CHAN + d];
    float o0 = mat0 + sq + sc0;
    out[n * 128 + layer * CHAN + d] = o0;
    h0out[n * CHAN + d] = o0;

    if (layer == 0) {
#pragma unroll
        for (int k = 0; k < 3; k++) {
            float v = mat1[k] + A0d * A1d[k]
                    + A2d[k * 3 + 0] * A1d[0] + A2d[k * 3 + 1] * A1d[1] + A2d[k * 3 + 2] * A1d[2];
            g_h1[n * CHAN * 3 + d * 3 + k] = v;
        }
#pragma unroll
        for (int i = 0; i < 3; i++)
#pragma unroll
            for (int j = 0; j < 3; j++) {
                int k = i * 3 + j;
                g_h2[n * CHAN * 9 + d * 9 + k] = mat2[k] + A1d[i] * A1d[j] + A0d * A2d[k];
            }
    }
}

// ---------------- launch -----------------------------------------------------
extern "C" void kernel_launch(void* const* d_in, const int* in_sizes, int n_in,
                              void* d_out, int out_size) {
    const float* edge_vec = (const float*)d_in[0];
    const int*   species  = (const int*)d_in[1];
    const int*   eidx     = (const int*)d_in[2];
    const float* W_emb    = (const float*)d_in[3];
    const float* rw1      = (const float*)d_in[4];
    const float* rw2      = (const float*)d_in[5];
    const float* Wg       = (const float*)d_in[6];
    const float* Wsc      = (const float*)d_in[7];
    const float* Wmix     = (const float*)d_in[8];
    float* out = (float*)d_out;

    int E = in_sizes[0] / 3;
    int N = in_sizes[1];
    int CH = (E + CSZ - 1) / CSZ;

    int ztotal = CH * N + N;
    k_zero<<<2048, 256>>>(ztotal);
    k_geom<<<(E + 255) / 256, 256>>>(edge_vec, E);
    k_h0init<<<(N * CHAN + 255) / 256, 256>>>(species, W_emb, N);
    k_chunk<<<(CH + 255) / 256, 256>>>(eidx, E, N, CH);
    k_count<<<(N + 255) / 256, 256>>>(N, CH);
    k_scan<<<1, 1024>>>(N);
    k_colpre<<<(N + 255) / 256, 256>>>(N, CH);
    k_scatter<<<(E + 255) / 256, 256>>>(eidx, E, N);

    for (int layer = 0; layer < 2; layer++) {
        k_gate<<<N, CHAN>>>(Wg, layer);
        k_edge<<<E / 32, 256>>>(rw1, rw2, eidx, E, layer);
        k_gather<<<(N + 3) / 4, 128>>>(N);
        k_update<<<N, CHAN>>>(Wmix, Wsc, species, out, layer, N);
    }
}

// round 2
// speedup vs baseline: 1.2715x; 1.2715x over previous
#include <cuda_runtime.h>
#include <math.h>

// Dataset is fixed: N=4000, E=64000, C=64
#define NMAX 4000
#define EMAX 64000
#define CHAN 64
#define NB 8
#define NK 13           // rank0(1) + rank1(3) + rank2(9)

// ---------------- scratch (static device globals) ----------------------------
__device__ float g_ef[EMAX * NB];            // radial basis per edge (edge order)
__device__ float g_Y[EMAX * NK];             // harmonics (edge order)
__device__ float g_Yp[EMAX * NK];            // harmonics (sorted-by-dst order)
__device__ float g_z[(size_t)EMAX * 192];    // messages, stored at sorted position
__device__ float g_A[NMAX * CHAN * NK];      // node features A[n][c][k]
__device__ float g_h0a[NMAX * CHAN];
__device__ float g_h0b[NMAX * CHAN];
__device__ float g_h1[NMAX * CHAN * 3];
__device__ float g_h2[NMAX * CHAN * 9];
__device__ float g_s[NMAX * CHAN];           // gate scalars
__device__ int   g_cnt[NMAX];
__device__ int   g_off[NMAX + 1];
__device__ int   g_cur[NMAX];                // atomic cursors
__device__ int   g_pos[EMAX];                // sorted position of edge e

// ---------------- setup kernels ----------------------------------------------
__global__ void k_zero_cnt(int N) {
    int i = blockIdx.x * blockDim.x + threadIdx.x;
    if (i < N) g_cnt[i] = 0;
}

// geometry: r, u, bessel * cutoff (sin recurrence), harmonics Y0..Y2
__global__ void k_geom(const float* __restrict__ ev, int E) {
    int e = blockIdx.x * blockDim.x + threadIdx.x;
    if (e >= E) return;
    float vx = ev[3 * e], vy = ev[3 * e + 1], vz = ev[3 * e + 2];
    float r = sqrtf(vx * vx + vy * vy + vz * vz);
    float inv = 1.f / r;
    float ux = vx * inv, uy = vy * inv, uz = vz * inv;
    float x = r * (1.f / 6.f);
    float fc = 0.f;
    if (x < 1.f) {
        float x2 = x * x;
        float x5 = x2 * x2 * x;
        fc = 1.f - 21.f * x5 + 35.f * x5 * x - 15.f * x5 * x2;
    }
    float pref = sqrtf(2.f / 6.f) * inv * fc;
    const float PI = 3.14159265358979323846f;
    float a = PI * x;
    float s1, c1;
    __sincosf(a, &s1, &c1);
    float twoc = 2.f * c1;
    float skm = 0.f, sk = s1;           // sin(0), sin(a)
    float* efp = g_ef + e * NB;
#pragma unroll
    for (int n = 0; n < NB; n++) {
        efp[n] = pref * sk;
        float nx = twoc * sk - skm;     // sin((n+2)a)
        skm = sk; sk = nx;
    }
    float* Y = g_Y + e * NK;
    Y[0] = 1.f;
    Y[1] = ux; Y[2] = uy; Y[3] = uz;
    Y[4] = ux * ux; Y[5] = ux * uy; Y[6] = ux * uz;
    Y[7] = uy * ux; Y[8] = uy * uy; Y[9] = uy * uz;
    Y[10] = uz * ux; Y[11] = uz * uy; Y[12] = uz * uz;
}

__global__ void k_h0init(const int* __restrict__ spec, const float* __restrict__ Wemb, int N) {
    int i = blockIdx.x * blockDim.x + threadIdx.x;
    if (i >= N * CHAN) return;
    int n = i >> 6, c = i & 63;
    g_h0a[i] = Wemb[spec[n] * CHAN + c];
}

// count edges per dst
__global__ void k_count(const int* __restrict__ eidx, int E) {
    int e = blockIdx.x * blockDim.x + threadIdx.x;
    if (e >= E) return;
    atomicAdd(&g_cnt[eidx[E + e]], 1);
}

// exclusive scan of g_cnt -> g_off (single block); also init cursors
__global__ void k_scan(int N) {
    __shared__ int sh[1024];
    __shared__ int carry_s;
    int t = threadIdx.x;
    if (t == 0) carry_s = 0;
    __syncthreads();
    int ntile = (N + 1023) / 1024;
    for (int tile = 0; tile < ntile; tile++) {
        int i = tile * 1024 + t;
        int v = (i < N) ? g_cnt[i] : 0;
        sh[t] = v;
        __syncthreads();
        for (int o = 1; o < 1024; o <<= 1) {
            int add = (t >= o) ? sh[t - o] : 0;
            __syncthreads();
            sh[t] += add;
            __syncthreads();
        }
        int incl = sh[t];
        int carry = carry_s;
        if (i < N) {
            int excl = carry + incl - v;
            g_off[i] = excl;
            g_cur[i] = excl;
        }
        if (i == N - 1) g_off[N] = carry + incl;
        __syncthreads();
        if (t == 1023) carry_s = carry + incl;
        __syncthreads();
    }
}

// assign sorted positions via atomic cursors; copy Y into sorted order
__global__ void k_place(const int* __restrict__ eidx, int E) {
    int e = blockIdx.x * blockDim.x + threadIdx.x;
    if (e >= E) return;
    int d = eidx[E + e];
    int pos = atomicAdd(&g_cur[d], 1);
    g_pos[e] = pos;
    const float* y = g_Y + e * NK;
    float* yp = g_Yp + pos * NK;
#pragma unroll
    for (int k = 0; k < NK; k++) yp[k] = y[k];
}

// ---------------- per-layer kernels ------------------------------------------
// s = h0 @ W_gate[layer];  4 nodes per 256-thread block
__global__ void k_gate(const float* __restrict__ Wg, int layer, int N) {
    __shared__ float sh0[4][CHAN];
    int g = threadIdx.x >> 6;
    int c = threadIdx.x & 63;
    int n = blockIdx.x * 4 + g;
    if (n >= N) return;
    const float* h0 = (layer == 0) ? g_h0a : g_h0b;
    sh0[g][c] = h0[n * CHAN + c];
    __syncthreads();
    const float* W = Wg + layer * CHAN * CHAN;
    float acc = 0.f;
#pragma unroll 8
    for (int d = 0; d < CHAN; d++) acc += sh0[g][d] * W[d * CHAN + c];
    g_s[n * CHAN + c] = acc;
}

// per-edge: hidden = silu(ef@W1); s_e (gate + density trick); z = (hidden@W2)*s_e
// written to sorted row g_pos[e]. 32 edges/block, 256 threads.
__global__ void k_edge(const float* __restrict__ rw1, const float* __restrict__ rw2,
                       const int* __restrict__ eidx, int E, int layer) {
    __shared__ float shH[64][32];   // hidden transposed [j][edge]
    __shared__ float shS[32][65];   // s_e [edge][c], padded
    __shared__ int   shPos[32];
    int e0 = blockIdx.x * 32;
    int tid = threadIdx.x;
    const float* W1 = rw1 + layer * NB * CHAN;

    if (tid < 32) shPos[tid] = g_pos[e0 + tid];

#pragma unroll
    for (int it = 0; it < 8; it++) {
        int idx = it * 256 + tid;
        int el = idx & 31;
        int c = idx >> 5;
        int e = e0 + el;
        const float* ef = g_ef + e * NB;
        float h = 0.f;
#pragma unroll
        for (int i = 0; i < NB; i++) h += ef[i] * W1[i * CHAN + c];
        h = h * (1.f / (1.f + __expf(-h)));   // silu
        shH[c][el] = h;

        int src = eidx[e];
        float se = g_s[src * CHAN + c];
        if (layer > 0) {
            const float* y = g_Y + e * NK;
            const float* h1 = g_h1 + src * CHAN * 3 + c * 3;
            se += h1[0] * y[1] + h1[1] * y[2] + h1[2] * y[3];
            const float* h2 = g_h2 + src * CHAN * 9 + c * 9;
#pragma unroll
            for (int j = 0; j < 9; j++) se += h2[j] * y[4 + j];
        }
        shS[el][c] = se;
    }
    __syncthreads();

    // z[pos][L][c] = (sum_j hidden[e][j] * W2[j][L*64+c]) * s_e[e][c]
    if (tid < 192) {
        int L = tid >> 6, c = tid & 63;
        const float* w2p = rw2 + layer * CHAN * 256 + L * CHAN + c;
        float acc[32];
#pragma unroll
        for (int q = 0; q < 32; q++) acc[q] = 0.f;
#pragma unroll 4
        for (int j = 0; j < 64; j++) {
            float w = w2p[j * 256];
            const float4* hp = reinterpret_cast<const float4*>(shH[j]);
#pragma unroll
            for (int q = 0; q < 8; q++) {
                float4 v = hp[q];
                acc[4 * q + 0] += v.x * w;
                acc[4 * q + 1] += v.y * w;
                acc[4 * q + 2] += v.z * w;
                acc[4 * q + 3] += v.w * w;
            }
        }
        int col = L * CHAN + c;
#pragma unroll
        for (int el = 0; el < 32; el++) {
            g_z[(size_t)shPos[el] * 192 + col] = acc[el] * shS[el][c];
        }
    }
}

// gather: warp per node; z and Yp rows are contiguous per node
__global__ void k_gather(int N) {
    int warp = threadIdx.x >> 5;
    int lane = threadIdx.x & 31;
    int node = blockIdx.x * 4 + warp;
    if (node >= N) return;
    float a0[NK], a1[NK];
#pragma unroll
    for (int k = 0; k < NK; k++) { a0[k] = 0.f; a1[k] = 0.f; }
    int beg = g_off[node], end = g_off[node + 1];
    for (int i = beg; i < end; i++) {
        const float* zp = g_z + (size_t)i * 192;
        float z0a = zp[lane],       z0b = zp[32 + lane];
        float z1a = zp[64 + lane],  z1b = zp[96 + lane];
        float z2a = zp[128 + lane], z2b = zp[160 + lane];
        const float* y = g_Yp + i * NK;
        a0[0] += z0a; a1[0] += z0b;
#pragma unroll
        for (int k = 1; k < 4; k++) {
            float yv = y[k];
            a0[k] += z1a * yv; a1[k] += z1b * yv;
        }
#pragma unroll
        for (int k = 4; k < NK; k++) {
            float yv = y[k];
            a0[k] += z2a * yv; a1[k] += z2b * yv;
        }
    }
    const float inv = 1.f / 16.f;
    float* Ap = g_A + node * CHAN * NK;
#pragma unroll
    for (int k = 0; k < NK; k++) {
        Ap[lane * NK + k] = a0[k] * inv;
        Ap[(lane + 32) * NK + k] = a1[k] * inv;
    }
}

// self-contraction + output
__global__ void k_update(const float* __restrict__ Wmix, const float* __restrict__ Wsc,
                         const int* __restrict__ spec, float* __restrict__ out,
                         int layer, int N) {
    __shared__ float sA[CHAN * NK];
    int n = blockIdx.x;
    int d = threadIdx.x;
    for (int i = d; i < CHAN * NK; i += CHAN) sA[i] = g_A[n * CHAN * NK + i];
    __syncthreads();

    const float* h0in = (layer == 0) ? g_h0a : g_h0b;
    float* h0out = (layer == 0) ? g_h0b : g_h0a;

    float A0d = sA[d * NK];
    float A1d[3], A2d[9];
#pragma unroll
    for (int k = 0; k < 3; k++) A1d[k] = sA[d * NK + 1 + k];
#pragma unroll
    for (int k = 0; k < 9; k++) A2d[k] = sA[d * NK + 4 + k];

    const float* Wm = Wmix + layer * 3 * CHAN * CHAN;
    float mat0 = 0.f;
    float mat1[3] = {0.f, 0.f, 0.f};
    float mat2[9] = {0.f, 0.f, 0.f, 0.f, 0.f, 0.f, 0.f, 0.f, 0.f};
    for (int c = 0; c < CHAN; c++) {
        mat0 += sA[c * NK] * Wm[c * CHAN + d];
        if (layer == 0) {
            float w1m = Wm[CHAN * CHAN + c * CHAN + d];
#pragma unroll
            for (int k = 0; k < 3; k++) mat1[k] += sA[c * NK + 1 + k] * w1m;
            float w2m = Wm[2 * CHAN * CHAN + c * CHAN + d];
#pragma unroll
            for (int k = 0; k < 9; k++) mat2[k] += sA[c * NK + 4 + k] * w2m;
        }
    }
    float sq = 0.f;
#pragma unroll
    for (int k = 0; k < 3; k++) sq += A1d[k] * A1d[k];
#pragma unroll
    for (int k = 0; k < 9; k++) sq += A2d[k] * A2d[k];

    int sp = spec[n];
    float sc0 = Wsc[layer * 10 * CHAN + sp * CHAN + d] * h0in[n * CHAN + d];
    float o0 = mat0 + sq + sc0;
    out[n * 128 + layer * CHAN + d] = o0;
    h0out[n * CHAN + d] = o0;

    if (layer == 0) {
#pragma unroll
        for (int k = 0; k < 3; k++) {
            float v = mat1[k] + A0d * A1d[k]
                    + A2d[k * 3 + 0] * A1d[0] + A2d[k * 3 + 1] * A1d[1] + A2d[k * 3 + 2] * A1d[2];
            g_h1[n * CHAN * 3 + d * 3 + k] = v;
        }
#pragma unroll
        for (int i = 0; i < 3; i++)
#pragma unroll
            for (int j = 0; j < 3; j++) {
                int k = i * 3 + j;
                g_h2[n * CHAN * 9 + d * 9 + k] = mat2[k] + A1d[i] * A1d[j] + A0d * A2d[k];
            }
    }
}

// ---------------- launch -----------------------------------------------------
extern "C" void kernel_launch(void* const* d_in, const int* in_sizes, int n_in,
                              void* d_out, int out_size) {
    const float* edge_vec = (const float*)d_in[0];
    const int*   species  = (const int*)d_in[1];
    const int*   eidx     = (const int*)d_in[2];
    const float* W_emb    = (const float*)d_in[3];
    const float* rw1      = (const float*)d_in[4];
    const float* rw2      = (const float*)d_in[5];
    const float* Wg       = (const float*)d_in[6];
    const float* Wsc      = (const float*)d_in[7];
    const float* Wmix     = (const float*)d_in[8];
    float* out = (float*)d_out;

    int E = in_sizes[0] / 3;
    int N = in_sizes[1];

    k_zero_cnt<<<(N + 255) / 256, 256>>>(N);
    k_geom<<<(E + 255) / 256, 256>>>(edge_vec, E);
    k_h0init<<<(N * CHAN + 255) / 256, 256>>>(species, W_emb, N);
    k_count<<<(E + 255) / 256, 256>>>(eidx, E);
    k_scan<<<1, 1024>>>(N);
    k_place<<<(E + 255) / 256, 256>>>(eidx, E);

    for (int layer = 0; layer < 2; layer++) {
        k_gate<<<(N + 3) / 4, 256>>>(Wg, layer, N);
        k_edge<<<E / 32, 256>>>(rw1, rw2, eidx, E, layer);
        k_gather<<<(N + 3) / 4, 128>>>(N);
        k_update<<<N, CHAN>>>(Wmix, Wsc, species, out, layer, N);
    }
}

// round 3
// speedup vs baseline: 2.1193x; 1.6668x over previous
#include <cuda_runtime.h>
#include <math.h>

// Dataset is fixed: N=4000, E=64000, C=64
#define NMAX 4000
#define EMAX 64000
#define CHAN 64
#define NB 8
#define NK 13           // rank0(1) + rank1(3) + rank2(9)

// ---------------- scratch (static device globals) ----------------------------
__device__ float g_ef[EMAX * NB];            // radial basis per edge (edge order)
__device__ float g_Y[EMAX * NK];             // harmonics (edge order)
__device__ float g_Yp[EMAX * NK];            // harmonics (sorted-by-dst order)
__device__ float g_z[(size_t)EMAX * 192];    // messages, stored at sorted position
__device__ float g_A[NMAX * CHAN * NK];      // node features A[n][c][k]
__device__ float g_h0a[NMAX * CHAN];
__device__ float g_h0b[NMAX * CHAN];
__device__ float g_h1[NMAX * CHAN * 3];
__device__ float g_h2[NMAX * CHAN * 9];
__device__ float g_s[NMAX * CHAN];           // gate scalars
__device__ int   g_cnt[NMAX];
__device__ int   g_off[NMAX + 1];
__device__ int   g_cur[NMAX];                // atomic cursors
__device__ int   g_pos[EMAX];                // sorted position of edge e

// packed f32x2 FMA (Blackwell): d = a*b + c lanewise on two fp32
__device__ __forceinline__ unsigned long long ffma2(unsigned long long a,
                                                    unsigned long long b,
                                                    unsigned long long c) {
    unsigned long long d;
    asm("fma.rn.f32x2 %0, %1, %2, %3;" : "=l"(d) : "l"(a), "l"(b), "l"(c));
    return d;
}

// ---------------- setup kernels ----------------------------------------------
__global__ void k_zero_cnt(int N) {
    int i = blockIdx.x * blockDim.x + threadIdx.x;
    if (i < N) g_cnt[i] = 0;
}

__global__ void k_geom(const float* __restrict__ ev, int E) {
    int e = blockIdx.x * blockDim.x + threadIdx.x;
    if (e >= E) return;
    float vx = ev[3 * e], vy = ev[3 * e + 1], vz = ev[3 * e + 2];
    float r = sqrtf(vx * vx + vy * vy + vz * vz);
    float inv = 1.f / r;
    float ux = vx * inv, uy = vy * inv, uz = vz * inv;
    float x = r * (1.f / 6.f);
    float fc = 0.f;
    if (x < 1.f) {
        float x2 = x * x;
        float x5 = x2 * x2 * x;
        fc = 1.f - 21.f * x5 + 35.f * x5 * x - 15.f * x5 * x2;
    }
    float pref = sqrtf(2.f / 6.f) * inv * fc;
    const float PI = 3.14159265358979323846f;
    float a = PI * x;
    float s1, c1;
    __sincosf(a, &s1, &c1);
    float twoc = 2.f * c1;
    float skm = 0.f, sk = s1;
    float* efp = g_ef + e * NB;
#pragma unroll
    for (int n = 0; n < NB; n++) {
        efp[n] = pref * sk;
        float nx = twoc * sk - skm;
        skm = sk; sk = nx;
    }
    float* Y = g_Y + e * NK;
    Y[0] = 1.f;
    Y[1] = ux; Y[2] = uy; Y[3] = uz;
    Y[4] = ux * ux; Y[5] = ux * uy; Y[6] = ux * uz;
    Y[7] = uy * ux; Y[8] = uy * uy; Y[9] = uy * uz;
    Y[10] = uz * ux; Y[11] = uz * uy; Y[12] = uz * uz;
}

__global__ void k_h0init(const int* __restrict__ spec, const float* __restrict__ Wemb, int N) {
    int i = blockIdx.x * blockDim.x + threadIdx.x;
    if (i >= N * CHAN) return;
    int n = i >> 6, c = i & 63;
    g_h0a[i] = Wemb[spec[n] * CHAN + c];
}

__global__ void k_count(const int* __restrict__ eidx, int E) {
    int e = blockIdx.x * blockDim.x + threadIdx.x;
    if (e >= E) return;
    atomicAdd(&g_cnt[eidx[E + e]], 1);
}

__global__ void k_scan(int N) {
    __shared__ int sh[1024];
    __shared__ int carry_s;
    int t = threadIdx.x;
    if (t == 0) carry_s = 0;
    __syncthreads();
    int ntile = (N + 1023) / 1024;
    for (int tile = 0; tile < ntile; tile++) {
        int i = tile * 1024 + t;
        int v = (i < N) ? g_cnt[i] : 0;
        sh[t] = v;
        __syncthreads();
        for (int o = 1; o < 1024; o <<= 1) {
            int add = (t >= o) ? sh[t - o] : 0;
            __syncthreads();
            sh[t] += add;
            __syncthreads();
        }
        int incl = sh[t];
        int carry = carry_s;
        if (i < N) {
            int excl = carry + incl - v;
            g_off[i] = excl;
            g_cur[i] = excl;
        }
        if (i == N - 1) g_off[N] = carry + incl;
        __syncthreads();
        if (t == 1023) carry_s = carry + incl;
        __syncthreads();
    }
}

__global__ void k_place(const int* __restrict__ eidx, int E) {
    int e = blockIdx.x * blockDim.x + threadIdx.x;
    if (e >= E) return;
    int d = eidx[E + e];
    int pos = atomicAdd(&g_cur[d], 1);
    g_pos[e] = pos;
    const float* y = g_Y + e * NK;
    float* yp = g_Yp + pos * NK;
#pragma unroll
    for (int k = 0; k < NK; k++) yp[k] = y[k];
}

// ---------------- per-layer kernels ------------------------------------------
__global__ void k_gate(const float* __restrict__ Wg, int layer, int N) {
    __shared__ float sh0[4][CHAN];
    int g = threadIdx.x >> 6;
    int c = threadIdx.x & 63;
    int n = blockIdx.x * 4 + g;
    if (n >= N) return;
    const float* h0 = (layer == 0) ? g_h0a : g_h0b;
    sh0[g][c] = h0[n * CHAN + c];
    __syncthreads();
    const float* W = Wg + layer * CHAN * CHAN;
    float acc = 0.f;
#pragma unroll 8
    for (int d = 0; d < CHAN; d++) acc += sh0[g][d] * W[d * CHAN + c];
    g_s[n * CHAN + c] = acc;
}

// per-edge: hidden = silu(ef@W1); s_e (gate + density trick); z = (hidden@W2)*s_e
// 32 edges/block, 192 threads. Phase 3 uses packed f32x2 FMAs (2 edges/reg).
__global__ void __launch_bounds__(192) k_edge(
        const float* __restrict__ rw1, const float* __restrict__ rw2,
        const int* __restrict__ eidx, int E, int layer) {
    __shared__ __align__(16) float shH[64][36];  // hidden [j][edge], 144B rows (16B aligned)
    __shared__ float shS[32][64];                // s_e [edge][c]
    __shared__ int   shPos[32];
    int e0 = blockIdx.x * 32;
    int tid = threadIdx.x;
    const float* W1 = rw1 + layer * NB * CHAN;

    if (tid < 32) shPos[tid] = g_pos[e0 + tid];

    // phases 1+2: c-fastest mapping => coalesced g_s / g_h1 / g_h2 reads
    for (int idx = tid; idx < 32 * CHAN; idx += 192) {
        int c = idx & 63;
        int el = idx >> 6;
        int e = e0 + el;
        const float* ef = g_ef + e * NB;
        float h = 0.f;
#pragma unroll
        for (int i = 0; i < NB; i++) h += ef[i] * W1[i * CHAN + c];
        h = h * (1.f / (1.f + __expf(-h)));   // silu
        shH[c][el] = h;

        int src = eidx[e];
        float se = g_s[src * CHAN + c];
        if (layer > 0) {
            const float* y = g_Y + e * NK;
            const float* h1 = g_h1 + src * CHAN * 3 + c * 3;
            se += h1[0] * y[1] + h1[1] * y[2] + h1[2] * y[3];
            const float* h2 = g_h2 + src * CHAN * 9 + c * 9;
#pragma unroll
            for (int j = 0; j < 9; j++) se += h2[j] * y[4 + j];
        }
        shS[el][c] = se;
    }
    __syncthreads();

    // phase 3: each thread owns one output column (L,c); 16 packed accumulators
    // cover 32 edges. z[pos][L*64+c] = (sum_j H[j][e] * W2[j][L*64+c]) * s_e[e][c]
    {
        int L = tid >> 6, c = tid & 63;
        const float* w2p = rw2 + layer * CHAN * 256 + L * CHAN + c;
        unsigned long long acc[16];
#pragma unroll
        for (int m = 0; m < 16; m++) acc[m] = 0ull;

#pragma unroll 2
        for (int jb = 0; jb < 64; jb += 8) {
            unsigned long long wp[8];
#pragma unroll
            for (int u = 0; u < 8; u++) {
                unsigned int wi = __float_as_uint(w2p[(jb + u) * 256]);
                asm("mov.b64 %0, {%1, %1};" : "=l"(wp[u]) : "r"(wi));
            }
#pragma unroll
            for (int u = 0; u < 8; u++) {
                const double2* dp = reinterpret_cast<const double2*>(&shH[jb + u][0]);
#pragma unroll
                for (int q = 0; q < 8; q++) {
                    double2 dv = dp[q];
                    acc[2 * q]     = ffma2(__double_as_longlong(dv.x), wp[u], acc[2 * q]);
                    acc[2 * q + 1] = ffma2(__double_as_longlong(dv.y), wp[u], acc[2 * q + 1]);
                }
            }
        }
        int col = L * CHAN + c;
#pragma unroll
        for (int m = 0; m < 16; m++) {
            float lo = __uint_as_float((unsigned int)(acc[m] & 0xffffffffull));
            float hi = __uint_as_float((unsigned int)(acc[m] >> 32));
            int ea = 2 * m, eb = 2 * m + 1;
            g_z[(size_t)shPos[ea] * 192 + col] = lo * shS[ea][c];
            g_z[(size_t)shPos[eb] * 192 + col] = hi * shS[eb][c];
        }
    }
}

// gather: warp per node; z and Yp rows are contiguous per node
__global__ void k_gather(int N) {
    int warp = threadIdx.x >> 5;
    int lane = threadIdx.x & 31;
    int node = blockIdx.x * 4 + warp;
    if (node >= N) return;
    float a0[NK], a1[NK];
#pragma unroll
    for (int k = 0; k < NK; k++) { a0[k] = 0.f; a1[k] = 0.f; }
    int beg = g_off[node], end = g_off[node + 1];
#pragma unroll 2
    for (int i = beg; i < end; i++) {
        const float* zp = g_z + (size_t)i * 192;
        float z0a = zp[lane],       z0b = zp[32 + lane];
        float z1a = zp[64 + lane],  z1b = zp[96 + lane];
        float z2a = zp[128 + lane], z2b = zp[160 + lane];
        const float* y = g_Yp + i * NK;
        a0[0] += z0a; a1[0] += z0b;
#pragma unroll
        for (int k = 1; k < 4; k++) {
            float yv = y[k];
            a0[k] += z1a * yv; a1[k] += z1b * yv;
        }
#pragma unroll
        for (int k = 4; k < NK; k++) {
            float yv = y[k];
            a0[k] += z2a * yv; a1[k] += z2b * yv;
        }
    }
    const float inv = 1.f / 16.f;
    float* Ap = g_A + node * CHAN * NK;
#pragma unroll
    for (int k = 0; k < NK; k++) {
        Ap[lane * NK + k] = a0[k] * inv;
        Ap[(lane + 32) * NK + k] = a1[k] * inv;
    }
}

// self-contraction + output
__global__ void k_update(const float* __restrict__ Wmix, const float* __restrict__ Wsc,
                         const int* __restrict__ spec, float* __restrict__ out,
                         int layer, int N) {
    __shared__ float sA[CHAN * NK];
    int n = blockIdx.x;
    int d = threadIdx.x;
    for (int i = d; i < CHAN * NK; i += CHAN) sA[i] = g_A[n * CHAN * NK + i];
    __syncthreads();

    const float* h0in = (layer == 0) ? g_h0a : g_h0b;
    float* h0out = (layer == 0) ? g_h0b : g_h0a;

    float A0d = sA[d * NK];
    float A1d[3], A2d[9];
#pragma unroll
    for (int k = 0; k < 3; k++) A1d[k] = sA[d * NK + 1 + k];
#pragma unroll
    for (int k = 0; k < 9; k++) A2d[k] = sA[d * NK + 4 + k];

    const float* Wm = Wmix + layer * 3 * CHAN * CHAN;
    float mat0 = 0.f;
    float mat1[3] = {0.f, 0.f, 0.f};
    float mat2[9] = {0.f, 0.f, 0.f, 0.f, 0.f, 0.f, 0.f, 0.f, 0.f};
    for (int c = 0; c < CHAN; c++) {
        mat0 += sA[c * NK] * Wm[c * CHAN + d];
        if (layer == 0) {
            float w1m = Wm[CHAN * CHAN + c * CHAN + d];
#pragma unroll
            for (int k = 0; k < 3; k++) mat1[k] += sA[c * NK + 1 + k] * w1m;
            float w2m = Wm[2 * CHAN * CHAN + c * CHAN + d];
#pragma unroll
            for (int k = 0; k < 9; k++) mat2[k] += sA[c * NK + 4 + k] * w2m;
        }
    }
    float sq = 0.f;
#pragma unroll
    for (int k = 0; k < 3; k++) sq += A1d[k] * A1d[k];
#pragma unroll
    for (int k = 0; k < 9; k++) sq += A2d[k] * A2d[k];

    int sp = spec[n];
    float sc0 = Wsc[layer * 10 * CHAN + sp * CHAN + d] * h0in[n * CHAN + d];
    float o0 = mat0 + sq + sc0;
    out[n * 128 + layer * CHAN + d] = o0;
    h0out[n * CHAN + d] = o0;

    if (layer == 0) {
#pragma unroll
        for (int k = 0; k < 3; k++) {
            float v = mat1[k] + A0d * A1d[k]
                    + A2d[k * 3 + 0] * A1d[0] + A2d[k * 3 + 1] * A1d[1] + A2d[k * 3 + 2] * A1d[2];
            g_h1[n * CHAN * 3 + d * 3 + k] = v;
        }
#pragma unroll
        for (int i = 0; i < 3; i++)
#pragma unroll
            for (int j = 0; j < 3; j++) {
                int k = i * 3 + j;
                g_h2[n * CHAN * 9 + d * 9 + k] = mat2[k] + A1d[i] * A1d[j] + A0d * A2d[k];
            }
    }
}

// ---------------- launch -----------------------------------------------------
extern "C" void kernel_launch(void* const* d_in, const int* in_sizes, int n_in,
                              void* d_out, int out_size) {
    const float* edge_vec = (const float*)d_in[0];
    const int*   species  = (const int*)d_in[1];
    const int*   eidx     = (const int*)d_in[2];
    const float* W_emb    = (const float*)d_in[3];
    const float* rw1      = (const float*)d_in[4];
    const float* rw2      = (const float*)d_in[5];
    const float* Wg       = (const float*)d_in[6];
    const float* Wsc      = (const float*)d_in[7];
    const float* Wmix     = (const float*)d_in[8];
    float* out = (float*)d_out;

    int E = in_sizes[0] / 3;
    int N = in_sizes[1];

    k_zero_cnt<<<(N + 255) / 256, 256>>>(N);
    k_geom<<<(E + 255) / 256, 256>>>(edge_vec, E);
    k_h0init<<<(N * CHAN + 255) / 256, 256>>>(species, W_emb, N);
    k_count<<<(E + 255) / 256, 256>>>(eidx, E);
    k_scan<<<1, 1024>>>(N);
    k_place<<<(E + 255) / 256, 256>>>(eidx, E);

    for (int layer = 0; layer < 2; layer++) {
        k_gate<<<(N + 3) / 4, 256>>>(Wg, layer, N);
        k_edge<<<E / 32, 192>>>(rw1, rw2, eidx, E, layer);
        k_gather<<<(N + 3) / 4, 128>>>(N);
        k_update<<<N, CHAN>>>(Wmix, Wsc, species, out, layer, N);
    }
}

// round 4
// speedup vs baseline: 2.2009x; 1.0385x over previous
#include <cuda_runtime.h>
#include <math.h>

// Dataset is fixed: N=4000, E=64000, C=64
#define NMAX 4000
#define EMAX 64000
#define CHAN 64
#define NB 8
#define NK 13           // rank0(1) + rank1(3) + rank2(9)

// ---------------- scratch (static device globals) ----------------------------
__device__ float g_ef[EMAX * NB];            // radial basis per edge (edge order)
__device__ float g_Y[EMAX * NK];             // harmonics (edge order)
__device__ float g_Yp[EMAX * NK];            // harmonics (sorted-by-dst order)
__device__ float g_z[(size_t)EMAX * 192];    // messages, stored at sorted position
__device__ float g_A[NMAX * CHAN * NK];      // node features A[n][c][k]
__device__ float g_h0a[NMAX * CHAN];
__device__ float g_h0b[NMAX * CHAN];
__device__ float g_h1[NMAX * 3 * CHAN];      // layout [n][k][c]
__device__ float g_h2[NMAX * 9 * CHAN];      // layout [n][k][c]
__device__ float g_s[NMAX * CHAN];           // gate scalars
__device__ int   g_cnt[NMAX];
__device__ int   g_off[NMAX + 1];
__device__ int   g_cur[NMAX];                // atomic cursors
__device__ int   g_pos[EMAX];                // sorted position of edge e

// packed f32x2 FMA (Blackwell): d = a*b + c lanewise on two fp32
__device__ __forceinline__ unsigned long long ffma2(unsigned long long a,
                                                    unsigned long long b,
                                                    unsigned long long c) {
    unsigned long long d;
    asm("fma.rn.f32x2 %0, %1, %2, %3;" : "=l"(d) : "l"(a), "l"(b), "l"(c));
    return d;
}

// ---------------- setup kernels ----------------------------------------------
// merged: zero g_cnt + h0 init
__global__ void k_init(const int* __restrict__ spec, const float* __restrict__ Wemb, int N) {
    int i = blockIdx.x * blockDim.x + threadIdx.x;
    if (i < N) g_cnt[i] = 0;
    if (i >= N * CHAN) return;
    int n = i >> 6, c = i & 63;
    g_h0a[i] = Wemb[spec[n] * CHAN + c];
}

// geometry + dst histogram
__global__ void k_geom(const float* __restrict__ ev, const int* __restrict__ eidx, int E) {
    int e = blockIdx.x * blockDim.x + threadIdx.x;
    if (e >= E) return;
    float vx = ev[3 * e], vy = ev[3 * e + 1], vz = ev[3 * e + 2];
    float r = sqrtf(vx * vx + vy * vy + vz * vz);
    float inv = 1.f / r;
    float ux = vx * inv, uy = vy * inv, uz = vz * inv;
    float x = r * (1.f / 6.f);
    float fc = 0.f;
    if (x < 1.f) {
        float x2 = x * x;
        float x5 = x2 * x2 * x;
        fc = 1.f - 21.f * x5 + 35.f * x5 * x - 15.f * x5 * x2;
    }
    float pref = sqrtf(2.f / 6.f) * inv * fc;
    const float PI = 3.14159265358979323846f;
    float a = PI * x;
    float s1, c1;
    __sincosf(a, &s1, &c1);
    float twoc = 2.f * c1;
    float skm = 0.f, sk = s1;
    float* efp = g_ef + e * NB;
#pragma unroll
    for (int n = 0; n < NB; n++) {
        efp[n] = pref * sk;
        float nx = twoc * sk - skm;
        skm = sk; sk = nx;
    }
    float* Y = g_Y + e * NK;
    Y[0] = 1.f;
    Y[1] = ux; Y[2] = uy; Y[3] = uz;
    Y[4] = ux * ux; Y[5] = ux * uy; Y[6] = ux * uz;
    Y[7] = uy * ux; Y[8] = uy * uy; Y[9] = uy * uz;
    Y[10] = uz * ux; Y[11] = uz * uy; Y[12] = uz * uz;
    atomicAdd(&g_cnt[eidx[E + e]], 1);
}

__global__ void k_scan(int N) {
    __shared__ int sh[1024];
    __shared__ int carry_s;
    int t = threadIdx.x;
    if (t == 0) carry_s = 0;
    __syncthreads();
    int ntile = (N + 1023) / 1024;
    for (int tile = 0; tile < ntile; tile++) {
        int i = tile * 1024 + t;
        int v = (i < N) ? g_cnt[i] : 0;
        sh[t] = v;
        __syncthreads();
        for (int o = 1; o < 1024; o <<= 1) {
            int add = (t >= o) ? sh[t - o] : 0;
            __syncthreads();
            sh[t] += add;
            __syncthreads();
        }
        int incl = sh[t];
        int carry = carry_s;
        if (i < N) {
            int excl = carry + incl - v;
            g_off[i] = excl;
            g_cur[i] = excl;
        }
        if (i == N - 1) g_off[N] = carry + incl;
        __syncthreads();
        if (t == 1023) carry_s = carry + incl;
        __syncthreads();
    }
}

__global__ void k_place(const int* __restrict__ eidx, int E) {
    int e = blockIdx.x * blockDim.x + threadIdx.x;
    if (e >= E) return;
    int d = eidx[E + e];
    int pos = atomicAdd(&g_cur[d], 1);
    g_pos[e] = pos;
    const float* y = g_Y + e * NK;
    float* yp = g_Yp + pos * NK;
#pragma unroll
    for (int k = 0; k < NK; k++) yp[k] = y[k];
}

// ---------------- per-layer kernels ------------------------------------------
__global__ void k_gate(const float* __restrict__ Wg, int layer, int N) {
    __shared__ float sh0[4][CHAN];
    int g = threadIdx.x >> 6;
    int c = threadIdx.x & 63;
    int n = blockIdx.x * 4 + g;
    if (n >= N) return;
    const float* h0 = (layer == 0) ? g_h0a : g_h0b;
    sh0[g][c] = h0[n * CHAN + c];
    __syncthreads();
    const float* W = Wg + layer * CHAN * CHAN;
    float acc = 0.f;
#pragma unroll 8
    for (int d = 0; d < CHAN; d++) acc += sh0[g][d] * W[d * CHAN + c];
    g_s[n * CHAN + c] = acc;
}

// per-edge: hidden = silu(ef@W1); s_e (gate + density trick); z = (hidden@W2)*s_e
// 32 edges/block, 384 threads. Phase 3: thread = (column, edge-half), packed f32x2.
__global__ void __launch_bounds__(384) k_edge(
        const float* __restrict__ rw1, const float* __restrict__ rw2,
        const int* __restrict__ eidx, int E, int layer) {
    __shared__ __align__(16) float shH[64][36];  // hidden [j][edge], 144B rows
    __shared__ float shS[32][64];                // s_e [edge][c]
    __shared__ int   shPos[32];
    int e0 = blockIdx.x * 32;
    int tid = threadIdx.x;
    const float* W1 = rw1 + layer * NB * CHAN;

    if (tid < 32) shPos[tid] = g_pos[e0 + tid];

    // phases 1+2: c-fastest => coalesced g_s / g_h1 / g_h2 reads
    for (int idx = tid; idx < 32 * CHAN; idx += 384) {
        int c = idx & 63;
        int el = idx >> 6;
        int e = e0 + el;
        const float* ef = g_ef + e * NB;
        float h = 0.f;
#pragma unroll
        for (int i = 0; i < NB; i++) h += ef[i] * W1[i * CHAN + c];
        h = h * (1.f / (1.f + __expf(-h)));   // silu
        shH[c][el] = h;

        int src = eidx[e];
        float se = g_s[src * CHAN + c];
        if (layer > 0) {
            const float* y = g_Y + e * NK;
            const float* h1 = g_h1 + src * 3 * CHAN + c;
            se += h1[0] * y[1] + h1[CHAN] * y[2] + h1[2 * CHAN] * y[3];
            const float* h2 = g_h2 + src * 9 * CHAN + c;
#pragma unroll
            for (int j = 0; j < 9; j++) se += h2[j * CHAN] * y[4 + j];
        }
        shS[el][c] = se;
    }
    __syncthreads();

    // phase 3: thread -> (cidx in 0..191, half in 0..1); 8 packed acc = 16 edges
    {
        int cidx = tid % 192;
        int hf = tid / 192;
        int c = cidx & 63;
        const float* w2p = rw2 + layer * CHAN * 256 + cidx;
        unsigned long long acc[8];
#pragma unroll
        for (int m = 0; m < 8; m++) acc[m] = 0ull;

#pragma unroll
        for (int jb = 0; jb < 64; jb += 8) {
            unsigned long long wp[8];
#pragma unroll
            for (int u = 0; u < 8; u++) {
                unsigned int wi = __float_as_uint(w2p[(jb + u) * 256]);
                asm("mov.b64 %0, {%1, %1};" : "=l"(wp[u]) : "r"(wi));
            }
#pragma unroll
            for (int u = 0; u < 8; u++) {
                const double2* dp = reinterpret_cast<const double2*>(&shH[jb + u][hf * 16]);
#pragma unroll
                for (int q = 0; q < 4; q++) {
                    double2 dv = dp[q];
                    acc[2 * q]     = ffma2(__double_as_longlong(dv.x), wp[u], acc[2 * q]);
                    acc[2 * q + 1] = ffma2(__double_as_longlong(dv.y), wp[u], acc[2 * q + 1]);
                }
            }
        }
#pragma unroll
        for (int m = 0; m < 8; m++) {
            float lo = __uint_as_float((unsigned int)(acc[m] & 0xffffffffull));
            float hi = __uint_as_float((unsigned int)(acc[m] >> 32));
            int ea = hf * 16 + 2 * m, eb = ea + 1;
            g_z[(size_t)shPos[ea] * 192 + cidx] = lo * shS[ea][c];
            g_z[(size_t)shPos[eb] * 192 + cidx] = hi * shS[eb][c];
        }
    }
}

// gather: warp per node; z and Yp rows are contiguous per node
__global__ void k_gather(int N) {
    int warp = threadIdx.x >> 5;
    int lane = threadIdx.x & 31;
    int node = blockIdx.x * 4 + warp;
    if (node >= N) return;
    float a0[NK], a1[NK];
#pragma unroll
    for (int k = 0; k < NK; k++) { a0[k] = 0.f; a1[k] = 0.f; }
    int beg = g_off[node], end = g_off[node + 1];
#pragma unroll 2
    for (int i = beg; i < end; i++) {
        const float* zp = g_z + (size_t)i * 192;
        float z0a = zp[lane],       z0b = zp[32 + lane];
        float z1a = zp[64 + lane],  z1b = zp[96 + lane];
        float z2a = zp[128 + lane], z2b = zp[160 + lane];
        const float* y = g_Yp + i * NK;
        a0[0] += z0a; a1[0] += z0b;
#pragma unroll
        for (int k = 1; k < 4; k++) {
            float yv = y[k];
            a0[k] += z1a * yv; a1[k] += z1b * yv;
        }
#pragma unroll
        for (int k = 4; k < NK; k++) {
            float yv = y[k];
            a0[k] += z2a * yv; a1[k] += z2b * yv;
        }
    }
    const float inv = 1.f / 16.f;
    float* Ap = g_A + node * CHAN * NK;
#pragma unroll
    for (int k = 0; k < NK; k++) {
        Ap[lane * NK + k] = a0[k] * inv;
        Ap[(lane + 32) * NK + k] = a1[k] * inv;
    }
}

// self-contraction + output
__global__ void k_update(const float* __restrict__ Wmix, const float* __restrict__ Wsc,
                         const int* __restrict__ spec, float* __restrict__ out,
                         int layer, int N) {
    __shared__ float sA[CHAN * NK];
    int n = blockIdx.x;
    int d = threadIdx.x;
    for (int i = d; i < CHAN * NK; i += CHAN) sA[i] = g_A[n * CHAN * NK + i];
    __syncthreads();

    const float* h0in = (layer == 0) ? g_h0a : g_h0b;
    float* h0out = (layer == 0) ? g_h0b : g_h0a;

    float A0d = sA[d * NK];
    float A1d[3], A2d[9];
#pragma unroll
    for (int k = 0; k < 3; k++) A1d[k] = sA[d * NK + 1 + k];
#pragma unroll
    for (int k = 0; k < 9; k++) A2d[k] = sA[d * NK + 4 + k];

    const float* Wm = Wmix + layer * 3 * CHAN * CHAN;
    float mat0 = 0.f;
    float mat1[3] = {0.f, 0.f, 0.f};
    float mat2[9] = {0.f, 0.f, 0.f, 0.f, 0.f, 0.f, 0.f, 0.f, 0.f};
    for (int c = 0; c < CHAN; c++) {
        mat0 += sA[c * NK] * Wm[c * CHAN + d];
        if (layer == 0) {
            float w1m = Wm[CHAN * CHAN + c * CHAN + d];
#pragma unroll
            for (int k = 0; k < 3; k++) mat1[k] += sA[c * NK + 1 + k] * w1m;
            float w2m = Wm[2 * CHAN * CHAN + c * CHAN + d];
#pragma unroll
            for (int k = 0; k < 9; k++) mat2[k] += sA[c * NK + 4 + k] * w2m;
        }
    }
    float sq = 0.f;
#pragma unroll
    for (int k = 0; k < 3; k++) sq += A1d[k] * A1d[k];
#pragma unroll
    for (int k = 0; k < 9; k++) sq += A2d[k] * A2d[k];

    int sp = spec[n];
    float sc0 = Wsc[layer * 10 * CHAN + sp * CHAN + d] * h0in[n * CHAN + d];
    float o0 = mat0 + sq + sc0;
    out[n * 128 + layer * CHAN + d] = o0;
    h0out[n * CHAN + d] = o0;

    if (layer == 0) {
#pragma unroll
        for (int k = 0; k < 3; k++) {
            float v = mat1[k] + A0d * A1d[k]
                    + A2d[k * 3 + 0] * A1d[0] + A2d[k * 3 + 1] * A1d[1] + A2d[k * 3 + 2] * A1d[2];
            g_h1[n * 3 * CHAN + k * CHAN + d] = v;     // [n][k][c]
        }
#pragma unroll
        for (int i = 0; i < 3; i++)
#pragma unroll
            for (int j = 0; j < 3; j++) {
                int k = i * 3 + j;
                g_h2[n * 9 * CHAN + k * CHAN + d] = mat2[k] + A1d[i] * A1d[j] + A0d * A2d[k];
            }
    }
}

// ---------------- launch -----------------------------------------------------
extern "C" void kernel_launch(void* const* d_in, const int* in_sizes, int n_in,
                              void* d_out, int out_size) {
    const float* edge_vec = (const float*)d_in[0];
    const int*   species  = (const int*)d_in[1];
    const int*   eidx     = (const int*)d_in[2];
    const float* W_emb    = (const float*)d_in[3];
    const float* rw1      = (const float*)d_in[4];
    const float* rw2      = (const float*)d_in[5];
    const float* Wg       = (const float*)d_in[6];
    const float* Wsc      = (const float*)d_in[7];
    const float* Wmix     = (const float*)d_in[8];
    float* out = (float*)d_out;

    int E = in_sizes[0] / 3;
    int N = in_sizes[1];

    // launch index:                                          0
    k_init<<<(N * CHAN + 255) / 256, 256>>>(species, W_emb, N);
    k_geom<<<(E + 255) / 256, 256>>>(edge_vec, eidx, E);   // 1
    k_scan<<<1, 1024>>>(N);                                // 2
    k_place<<<(E + 255) / 256, 256>>>(eidx, E);            // 3

    for (int layer = 0; layer < 2; layer++) {
        k_gate<<<(N + 3) / 4, 256>>>(Wg, layer, N);        // 4
        k_edge<<<E / 32, 384>>>(rw1, rw2, eidx, E, layer); // 5  <- ncu -s 5 captures this
        k_gather<<<(N + 3) / 4, 128>>>(N);
        k_update<<<N, CHAN>>>(Wmix, Wsc, species, out, layer, N);
    }
}

// round 6
// speedup vs baseline: 2.4005x; 1.0907x over previous
#include <cuda_runtime.h>
#include <math.h>

// Dataset is fixed: N=4000, E=64000, C=64
#define NMAX 4000
#define EMAX 64000
#define CHAN 64
#define NB 8
#define NK 13           // rank0(1) + rank1(3) + rank2(9)

// ---------------- scratch (static device globals) ----------------------------
__device__ float g_ef[EMAX * NB];            // radial basis per edge (edge order)
__device__ float g_Y[EMAX * NK];             // harmonics (edge order)
__device__ float g_A[NMAX * CHAN * NK];      // node features A[n][c][k] (atomic accum)
__device__ float g_h0a[NMAX * CHAN];
__device__ float g_h0b[NMAX * CHAN];
__device__ float g_h1[NMAX * 3 * CHAN];      // layout [n][k][c]
__device__ float g_h2[NMAX * 9 * CHAN];      // layout [n][k][c]
__device__ float g_s[NMAX * CHAN];           // gate scalars
__device__ int   g_cur[NMAX];                // atomic cursors
__device__ int   g_eid[EMAX];                // sorted position -> original edge
__device__ int   g_dstp[EMAX];               // sorted position -> dst node

// packed f32x2 FMA (Blackwell)
__device__ __forceinline__ unsigned long long ffma2(unsigned long long a,
                                                    unsigned long long b,
                                                    unsigned long long c) {
    unsigned long long d;
    asm("fma.rn.f32x2 %0, %1, %2, %3;" : "=l"(d) : "l"(a), "l"(b), "l"(c));
    return d;
}

// ---------------- fused setup: geometry | h0-init + gate0 + zero A -----------
__global__ void k_geomgate(const float* __restrict__ ev, const int* __restrict__ spec,
                           const float* __restrict__ Wemb, const float* __restrict__ Wg,
                           int E, int N, int GB_E, int GB_N) {
    if ((int)blockIdx.x < GB_E) {
        // ---- geometry role ----
        int e = blockIdx.x * blockDim.x + threadIdx.x;
        if (e >= E) return;
        float vx = ev[3 * e], vy = ev[3 * e + 1], vz = ev[3 * e + 2];
        float r = sqrtf(vx * vx + vy * vy + vz * vz);
        float inv = 1.f / r;
        float ux = vx * inv, uy = vy * inv, uz = vz * inv;
        float x = r * (1.f / 6.f);
        float fc = 0.f;
        if (x < 1.f) {
            float x2 = x * x;
            float x5 = x2 * x2 * x;
            fc = 1.f - 21.f * x5 + 35.f * x5 * x - 15.f * x5 * x2;
        }
        float pref = sqrtf(2.f / 6.f) * inv * fc;
        const float PI = 3.14159265358979323846f;
        float a = PI * x;
        float s1, c1;
        __sincosf(a, &s1, &c1);
        float twoc = 2.f * c1;
        float skm = 0.f, sk = s1;
        float* efp = g_ef + e * NB;
#pragma unroll
        for (int n = 0; n < NB; n++) {
            efp[n] = pref * sk;
            float nx = twoc * sk - skm;
            skm = sk; sk = nx;
        }
        float* Y = g_Y + e * NK;
        Y[0] = 1.f;
        Y[1] = ux; Y[2] = uy; Y[3] = uz;
        Y[4] = ux * ux; Y[5] = ux * uy; Y[6] = ux * uz;
        Y[7] = uy * ux; Y[8] = uy * uy; Y[9] = uy * uz;
        Y[10] = uz * ux; Y[11] = uz * uy; Y[12] = uz * uz;
    } else {
        // ---- node role: h0 init + gate layer0 + zero A ----
        __shared__ float sh0[4][CHAN];
        int nb = blockIdx.x - GB_E;
        int g = threadIdx.x >> 6;
        int c = threadIdx.x & 63;
        int n = nb * 4 + g;
        // zero A (grid-stride across node-role blocks)
        int stride = GB_N * 256;
        for (int i = nb * 256 + threadIdx.x; i < N * CHAN * NK; i += stride) g_A[i] = 0.f;
        if (n >= N) return;
        float h0 = Wemb[spec[n] * CHAN + c];
        g_h0a[n * CHAN + c] = h0;
        sh0[g][c] = h0;
        __syncthreads();
        float acc = 0.f;
#pragma unroll 8
        for (int d = 0; d < CHAN; d++) acc += sh0[g][d] * Wg[d * CHAN + c];
        g_s[n * CHAN + c] = acc;
    }
}

// ---------------- histogram + exclusive scan (one block) ---------------------
__global__ void k_scanhist(const int* __restrict__ eidx, int E, int N) {
    __shared__ int hist[NMAX];
    __shared__ int sh[1024];
    __shared__ int carry_s;
    int t = threadIdx.x;
    for (int i = t; i < N; i += 1024) hist[i] = 0;
    if (t == 0) carry_s = 0;
    __syncthreads();
    for (int e = t; e < E; e += 1024) atomicAdd(&hist[eidx[E + e]], 1);
    __syncthreads();
    int ntile = (N + 1023) / 1024;
    for (int tile = 0; tile < ntile; tile++) {
        int i = tile * 1024 + t;
        int v = (i < N) ? hist[i] : 0;
        sh[t] = v;
        __syncthreads();
        for (int o = 1; o < 1024; o <<= 1) {
            int add = (t >= o) ? sh[t - o] : 0;
            __syncthreads();
            sh[t] += add;
            __syncthreads();
        }
        int incl = sh[t];
        int carry = carry_s;
        if (i < N) g_cur[i] = carry + incl - v;   // exclusive prefix
        __syncthreads();
        if (t == 1023) carry_s = carry + incl;
        __syncthreads();
    }
}

// assign sorted positions via atomic cursors
__global__ void k_place(const int* __restrict__ eidx, int E) {
    int e = blockIdx.x * blockDim.x + threadIdx.x;
    if (e >= E) return;
    int d = eidx[E + e];
    int pos = atomicAdd(&g_cur[d], 1);
    g_eid[pos] = e;
    g_dstp[pos] = d;
}

// ---------------- per-layer kernels ------------------------------------------
__global__ void k_gate(const float* __restrict__ Wg, int N) {
    __shared__ float sh0[4][CHAN];
    int g = threadIdx.x >> 6;
    int c = threadIdx.x & 63;
    int n = blockIdx.x * 4 + g;
    if (n >= N) return;
    sh0[g][c] = g_h0b[n * CHAN + c];
    __syncthreads();
    const float* W = Wg + CHAN * CHAN;   // layer 1 weights
    float acc = 0.f;
#pragma unroll 8
    for (int d = 0; d < CHAN; d++) acc += sh0[g][d] * W[d * CHAN + c];
    g_s[n * CHAN + c] = acc;
}

// fused edge kernel: radial MLP + gate + message + scatter-reduce into g_A.
// Block = 32 consecutive SORTED positions, 384 threads.
__global__ void __launch_bounds__(384) k_edge(
        const float* __restrict__ rw1, const float* __restrict__ rw2,
        const int* __restrict__ eidx, int E, int layer) {
    __shared__ __align__(16) float shH[64][36];  // hidden [j][edge]
    __shared__ float shS[32][64];                // s_e [edge][c]
    __shared__ float shY[32][NK];                // harmonics per sorted edge
    __shared__ int   shEid[32];
    __shared__ int   shDst[32];
    int p0 = blockIdx.x * 32;
    int tid = threadIdx.x;
    const float* W1 = rw1 + layer * NB * CHAN;

    if (tid < 32) {
        shEid[tid] = g_eid[p0 + tid];
        shDst[tid] = g_dstp[p0 + tid];
    }
    __syncthreads();

    // phases 1+2 over (el, c): hidden j=c and gate channel c
    for (int idx = tid; idx < 32 * CHAN; idx += 384) {
        int c = idx & 63;
        int el = idx >> 6;
        int e = shEid[el];
        const float* ef = g_ef + e * NB;
        float h = 0.f;
#pragma unroll
        for (int i = 0; i < NB; i++) h += ef[i] * W1[i * CHAN + c];
        h = h * (1.f / (1.f + __expf(-h)));   // silu
        shH[c][el] = h;

        if (c < NK) shY[el][c] = g_Y[e * NK + c];

        int src = eidx[e];
        float se = g_s[src * CHAN + c];
        if (layer > 0) {
            const float* y = g_Y + e * NK;
            const float* h1 = g_h1 + src * 3 * CHAN + c;
            se += h1[0] * y[1] + h1[CHAN] * y[2] + h1[2 * CHAN] * y[3];
            const float* h2 = g_h2 + src * 9 * CHAN + c;
#pragma unroll
            for (int j = 0; j < 9; j++) se += h2[j * CHAN] * y[4 + j];
        }
        shS[el][c] = se;
    }
    __syncthreads();

    // phase 3: thread -> (cidx 0..191, hf 0..1); GEMM via packed f32x2
    {
        int cidx = tid % 192;
        int hf = tid / 192;
        int c = cidx & 63;
        int L = cidx >> 6;
        const float* w2p = rw2 + layer * CHAN * 256 + cidx;
        unsigned long long acc[8];
#pragma unroll
        for (int m = 0; m < 8; m++) acc[m] = 0ull;

#pragma unroll
        for (int jb = 0; jb < 64; jb += 8) {
            unsigned long long wp[8];
#pragma unroll
            for (int u = 0; u < 8; u++) {
                unsigned int wi = __float_as_uint(w2p[(jb + u) * 256]);
                asm("mov.b64 %0, {%1, %1};" : "=l"(wp[u]) : "r"(wi));
            }
#pragma unroll
            for (int u = 0; u < 8; u++) {
                const double2* dp = reinterpret_cast<const double2*>(&shH[jb + u][hf * 16]);
#pragma unroll
                for (int q = 0; q < 4; q++) {
                    double2 dv = dp[q];
                    acc[2 * q]     = ffma2(__double_as_longlong(dv.x), wp[u], acc[2 * q]);
                    acc[2 * q + 1] = ffma2(__double_as_longlong(dv.y), wp[u], acc[2 * q + 1]);
                }
            }
        }
        // unpack z (message scalar per edge for this column)
        float z[16];
#pragma unroll
        for (int m = 0; m < 8; m++) {
            int ea = hf * 16 + 2 * m;
            z[2 * m]     = __uint_as_float((unsigned int)(acc[m] & 0xffffffffull)) * shS[ea][c];
            z[2 * m + 1] = __uint_as_float((unsigned int)(acc[m] >> 32)) * shS[ea + 1][c];
        }

        // scatter-reduce runs of equal dst (warp-uniform control flow)
        const float inv = 1.f / 16.f;
        float* Abase = g_A + (size_t)c * NK;
        if (L == 0) {
            float s0 = 0.f;
            int cur = shDst[hf * 16];
#pragma unroll
            for (int i = 0; i < 16; i++) {
                int el = hf * 16 + i;
                int d = shDst[el];
                if (d != cur) {
                    atomicAdd(&Abase[(size_t)cur * CHAN * NK + 0], s0 * inv);
                    s0 = 0.f; cur = d;
                }
                s0 += z[i];
            }
            atomicAdd(&Abase[(size_t)cur * CHAN * NK + 0], s0 * inv);
        } else if (L == 1) {
            float s1[3] = {0.f, 0.f, 0.f};
            int cur = shDst[hf * 16];
#pragma unroll
            for (int i = 0; i < 16; i++) {
                int el = hf * 16 + i;
                int d = shDst[el];
                if (d != cur) {
#pragma unroll
                    for (int k = 0; k < 3; k++) {
                        atomicAdd(&Abase[(size_t)cur * CHAN * NK + 1 + k], s1[k] * inv);
                        s1[k] = 0.f;
                    }
                    cur = d;
                }
                float zv = z[i];
#pragma unroll
                for (int k = 0; k < 3; k++) s1[k] += zv * shY[el][1 + k];
            }
#pragma unroll
            for (int k = 0; k < 3; k++)
                atomicAdd(&Abase[(size_t)cur * CHAN * NK + 1 + k], s1[k] * inv);
        } else {
            float s2[9];
#pragma unroll
            for (int k = 0; k < 9; k++) s2[k] = 0.f;
            int cur = shDst[hf * 16];
#pragma unroll
            for (int i = 0; i < 16; i++) {
                int el = hf * 16 + i;
                int d = shDst[el];
                if (d != cur) {
#pragma unroll
                    for (int k = 0; k < 9; k++) {
                        atomicAdd(&Abase[(size_t)cur * CHAN * NK + 4 + k], s2[k] * inv);
                        s2[k] = 0.f;
                    }
                    cur = d;
                }
                float zv = z[i];
#pragma unroll
                for (int k = 0; k < 9; k++) s2[k] += zv * shY[el][4 + k];
            }
#pragma unroll
            for (int k = 0; k < 9; k++)
                atomicAdd(&Abase[(size_t)cur * CHAN * NK + 4 + k], s2[k] * inv);
        }
    }
}

// self-contraction + output; re-zeros its A slice for the next layer
__global__ void k_update(const float* __restrict__ Wmix, const float* __restrict__ Wsc,
                         const int* __restrict__ spec, float* __restrict__ out,
                         int layer, int N) {
    __shared__ float sA[CHAN * NK];
    int n = blockIdx.x;
    int d = threadIdx.x;
    for (int i = d; i < CHAN * NK; i += CHAN) sA[i] = g_A[n * CHAN * NK + i];
    __syncthreads();
    // re-zero this node's A slice for next layer (safe: all loads done)
    for (int i = d; i < CHAN * NK; i += CHAN) g_A[n * CHAN * NK + i] = 0.f;

    const float* h0in = (layer == 0) ? g_h0a : g_h0b;
    float* h0out = (layer == 0) ? g_h0b : g_h0a;

    float A0d = sA[d * NK];
    float A1d[3], A2d[9];
#pragma unroll
    for (int k = 0; k < 3; k++) A1d[k] = sA[d * NK + 1 + k];
#pragma unroll
    for (int k = 0; k < 9; k++) A2d[k] = sA[d * NK + 4 + k];

    const float* Wm = Wmix + layer * 3 * CHAN * CHAN;
    float mat0 = 0.f;
    float mat1[3] = {0.f, 0.f, 0.f};
    float mat2[9] = {0.f, 0.f, 0.f, 0.f, 0.f, 0.f, 0.f, 0.f, 0.f};
    for (int c = 0; c < CHAN; c++) {
        mat0 += sA[c * NK] * Wm[c * CHAN + d];
        if (layer == 0) {
            float w1m = Wm[CHAN * CHAN + c * CHAN + d];
#pragma unroll
            for (int k = 0; k < 3; k++) mat1[k] += sA[c * NK + 1 + k] * w1m;
            float w2m = Wm[2 * CHAN * CHAN + c * CHAN + d];
#pragma unroll
            for (int k = 0; k < 9; k++) mat2[k] += sA[c * NK + 4 + k] * w2m;
        }
    }
    float sq = 0.f;
#pragma unroll
    for (int k = 0; k < 3; k++) sq += A1d[k] * A1d[k];
#pragma unroll
    for (int k = 0; k < 9; k++) sq += A2d[k] * A2d[k];

    int sp = spec[n];
    float sc0 = Wsc[layer * 10 * CHAN + sp * CHAN + d] * h0in[n * CHAN + d];
    float o0 = mat0 + sq + sc0;
    out[n * 128 + layer * CHAN + d] = o0;
    h0out[n * CHAN + d] = o0;

    if (layer == 0) {
#pragma unroll
        for (int k = 0; k < 3; k++) {
            float v = mat1[k] + A0d * A1d[k]
                    + A2d[k * 3 + 0] * A1d[0] + A2d[k * 3 + 1] * A1d[1] + A2d[k * 3 + 2] * A1d[2];
            g_h1[n * 3 * CHAN + k * CHAN + d] = v;     // [n][k][c]
        }
#pragma unroll
        for (int i = 0; i < 3; i++)
#pragma unroll
            for (int j = 0; j < 3; j++) {
                int k = i * 3 + j;
                g_h2[n * 9 * CHAN + k * CHAN + d] = mat2[k] + A1d[i] * A1d[j] + A0d * A2d[k];
            }
    }
}

// ---------------- launch -----------------------------------------------------
extern "C" void kernel_launch(void* const* d_in, const int* in_sizes, int n_in,
                              void* d_out, int out_size) {
    const float* edge_vec = (const float*)d_in[0];
    const int*   species  = (const int*)d_in[1];
    const int*   eidx     = (const int*)d_in[2];
    const float* W_emb    = (const float*)d_in[3];
    const float* rw1      = (const float*)d_in[4];
    const float* rw2      = (const float*)d_in[5];
    const float* Wg       = (const float*)d_in[6];
    const float* Wsc      = (const float*)d_in[7];
    const float* Wmix     = (const float*)d_in[8];
    float* out = (float*)d_out;

    int E = in_sizes[0] / 3;
    int N = in_sizes[1];
    int GB_E = (E + 255) / 256;
    int GB_N = (N + 3) / 4;

    k_geomgate<<<GB_E + GB_N, 256>>>(edge_vec, species, W_emb, Wg, E, N, GB_E, GB_N); // 0
    k_scanhist<<<1, 1024>>>(eidx, E, N);                                              // 1
    k_place<<<GB_E, 256>>>(eidx, E);                                                  // 2

    k_edge<<<E / 32, 384>>>(rw1, rw2, eidx, E, 0);                                    // 3 <- profiled
    k_update<<<N, CHAN>>>(Wmix, Wsc, species, out, 0, N);                             // 4
    k_gate<<<GB_N, 256>>>(Wg, N);                                                     // 5
    k_edge<<<E / 32, 384>>>(rw1, rw2, eidx, E, 1);                                    // 6
    k_update<<<N, CHAN>>>(Wmix, Wsc, species, out, 1, N);                             // 7
}

// round 8
// speedup vs baseline: 2.6078x; 1.0863x over previous
#include <cuda_runtime.h>
#include <math.h>

// Dataset is fixed: N=4000, E=64000, C=64
#define NMAX 4000
#define EMAX 64000
#define CHAN 64
#define NB 8
#define NY 9            // compact harmonics: ux,uy,uz,xx,xy,xz,yy,yz,zz
#define NKC 10          // compact A components: 1 + 3 + 6

// ---------------- scratch (static device globals) ----------------------------
__device__ float g_ef[EMAX * NB];            // radial basis per edge (edge order)
__device__ float g_Y[EMAX * NY];             // compact harmonics (edge order)
__device__ float g_A[NMAX * CHAN * NKC];     // node features A[n][c][k] compact
__device__ float g_h0a[NMAX * CHAN];
__device__ float g_h0b[NMAX * CHAN];
__device__ float g_h1[NMAX * 3 * CHAN];      // layout [n][k][c]
__device__ float g_h2[NMAX * 6 * CHAN];      // compact symmetric, layout [n][k][c]
__device__ float g_s[NMAX * CHAN];           // gate scalars
__device__ int   g_cur[NMAX];                // atomic cursors
__device__ int   g_eid[EMAX];                // sorted position -> original edge
__device__ int   g_dstp[EMAX];               // sorted position -> dst node

// packed f32x2 FMA (Blackwell)
__device__ __forceinline__ unsigned long long ffma2(unsigned long long a,
                                                    unsigned long long b,
                                                    unsigned long long c) {
    unsigned long long d;
    asm("fma.rn.f32x2 %0, %1, %2, %3;" : "=l"(d) : "l"(a), "l"(b), "l"(c));
    return d;
}

// ---------------- fused setup: geometry | h0-init + gate0 + zero A -----------
__global__ void k_geomgate(const float* __restrict__ ev, const int* __restrict__ spec,
                           const float* __restrict__ Wemb, const float* __restrict__ Wg,
                           int E, int N, int GB_E, int GB_N) {
    if ((int)blockIdx.x < GB_E) {
        int e = blockIdx.x * blockDim.x + threadIdx.x;
        if (e >= E) return;
        float vx = ev[3 * e], vy = ev[3 * e + 1], vz = ev[3 * e + 2];
        float r = sqrtf(vx * vx + vy * vy + vz * vz);
        float inv = 1.f / r;
        float ux = vx * inv, uy = vy * inv, uz = vz * inv;
        float x = r * (1.f / 6.f);
        float fc = 0.f;
        if (x < 1.f) {
            float x2 = x * x;
            float x5 = x2 * x2 * x;
            fc = 1.f - 21.f * x5 + 35.f * x5 * x - 15.f * x5 * x2;
        }
        float pref = sqrtf(2.f / 6.f) * inv * fc;
        const float PI = 3.14159265358979323846f;
        float a = PI * x;
        float s1, c1;
        __sincosf(a, &s1, &c1);
        float twoc = 2.f * c1;
        float skm = 0.f, sk = s1;
        float* efp = g_ef + e * NB;
#pragma unroll
        for (int n = 0; n < NB; n++) {
            efp[n] = pref * sk;
            float nx = twoc * sk - skm;
            skm = sk; sk = nx;
        }
        float* Y = g_Y + e * NY;
        Y[0] = ux; Y[1] = uy; Y[2] = uz;
        Y[3] = ux * ux; Y[4] = ux * uy; Y[5] = ux * uz;
        Y[6] = uy * uy; Y[7] = uy * uz; Y[8] = uz * uz;
    } else {
        __shared__ float sh0[4][CHAN];
        int nb = blockIdx.x - GB_E;
        int g = threadIdx.x >> 6;
        int c = threadIdx.x & 63;
        int n = nb * 4 + g;
        int stride = GB_N * 256;
        for (int i = nb * 256 + threadIdx.x; i < N * CHAN * NKC; i += stride) g_A[i] = 0.f;
        if (n >= N) return;
        float h0 = Wemb[spec[n] * CHAN + c];
        g_h0a[n * CHAN + c] = h0;
        sh0[g][c] = h0;
        __syncthreads();
        float acc = 0.f;
#pragma unroll 8
        for (int d = 0; d < CHAN; d++) acc += sh0[g][d] * Wg[d * CHAN + c];
        g_s[n * CHAN + c] = acc;
    }
}

// ---------------- histogram + exclusive scan (one block) ---------------------
__global__ void k_scanhist(const int* __restrict__ eidx, int E, int N) {
    __shared__ int hist[NMAX];
    __shared__ int sh[1024];
    __shared__ int carry_s;
    int t = threadIdx.x;
    for (int i = t; i < N; i += 1024) hist[i] = 0;
    if (t == 0) carry_s = 0;
    __syncthreads();
    for (int e = t; e < E; e += 1024) atomicAdd(&hist[eidx[E + e]], 1);
    __syncthreads();
    int ntile = (N + 1023) / 1024;
    for (int tile = 0; tile < ntile; tile++) {
        int i = tile * 1024 + t;
        int v = (i < N) ? hist[i] : 0;
        sh[t] = v;
        __syncthreads();
        for (int o = 1; o < 1024; o <<= 1) {
            int add = (t >= o) ? sh[t - o] : 0;
            __syncthreads();
            sh[t] += add;
            __syncthreads();
        }
        int incl = sh[t];
        int carry = carry_s;
        if (i < N) g_cur[i] = carry + incl - v;
        __syncthreads();
        if (t == 1023) carry_s = carry + incl;
        __syncthreads();
    }
}

__global__ void k_place(const int* __restrict__ eidx, int E) {
    int e = blockIdx.x * blockDim.x + threadIdx.x;
    if (e >= E) return;
    int d = eidx[E + e];
    int pos = atomicAdd(&g_cur[d], 1);
    g_eid[pos] = e;
    g_dstp[pos] = d;
}

// ---------------- per-layer kernels ------------------------------------------
__global__ void k_gate(const float* __restrict__ Wg, int N) {
    __shared__ float sh0[4][CHAN];
    int g = threadIdx.x >> 6;
    int c = threadIdx.x & 63;
    int n = blockIdx.x * 4 + g;
    if (n >= N) return;
    sh0[g][c] = g_h0b[n * CHAN + c];
    __syncthreads();
    const float* W = Wg + CHAN * CHAN;
    float acc = 0.f;
#pragma unroll 8
    for (int d = 0; d < CHAN; d++) acc += sh0[g][d] * W[d * CHAN + c];
    g_s[n * CHAN + c] = acc;
}

// fused edge kernel: radial MLP + gate + message + compact scatter-reduce.
// Block = 32 consecutive sorted positions, 384 threads (phase3: 192 active).
__global__ void __launch_bounds__(384) k_edge(
        const float* __restrict__ rw1, const float* __restrict__ rw2,
        const int* __restrict__ eidx, int E, int layer) {
    __shared__ __align__(16) float shH[64][36];  // hidden [j][edge]
    __shared__ float shS[32][64];                // s_e [edge][c]
    __shared__ float shYc[32][NY];               // compact harmonics per edge
    __shared__ float shEf[32][NB];               // staged radial basis
    __shared__ int   shEid[32];
    __shared__ int   shDst[32];
    int p0 = blockIdx.x * 32;
    int tid = threadIdx.x;
    const float* W1 = rw1 + layer * NB * CHAN;

    if (tid < 32) {
        shEid[tid] = g_eid[p0 + tid];
        shDst[tid] = g_dstp[p0 + tid];
    }
    __syncthreads();

    // stage ef + Y into smem (coalesced-ish; removes redundant broadcast LDG)
    if (tid < 256) {
        int el = tid >> 3, i = tid & 7;
        shEf[el][i] = g_ef[shEid[el] * NB + i];
    }
    for (int i = tid; i < 32 * NY; i += 384) {
        int el = i / NY, k = i % NY;
        shYc[el][k] = g_Y[shEid[el] * NY + k];
    }
    __syncthreads();

    // phases 1+2 over (el, c)
    for (int idx = tid; idx < 32 * CHAN; idx += 384) {
        int c = idx & 63;
        int el = idx >> 6;
        int e = shEid[el];
        float h = 0.f;
#pragma unroll
        for (int i = 0; i < NB; i++) h += shEf[el][i] * W1[i * CHAN + c];
        h = h * (1.f / (1.f + __expf(-h)));   // silu
        shH[c][el] = h;

        int src = eidx[e];
        float se = g_s[src * CHAN + c];
        if (layer > 0) {
            const float* y = shYc[el];
            const float* h1 = g_h1 + src * 3 * CHAN + c;
            se += h1[0] * y[0] + h1[CHAN] * y[1] + h1[2 * CHAN] * y[2];
            const float* h2 = g_h2 + src * 6 * CHAN + c;
            se += h2[0] * y[3] + 2.f * h2[CHAN] * y[4] + 2.f * h2[2 * CHAN] * y[5]
                + h2[3 * CHAN] * y[6] + 2.f * h2[4 * CHAN] * y[7] + h2[5 * CHAN] * y[8];
        }
        shS[el][c] = se;
    }
    __syncthreads();

    // phase 3: thread = one column (cidx 0..191) over all 32 edges
    if (tid < 192) {
        int cidx = tid;
        int c = cidx & 63;
        int L = cidx >> 6;
        const float* w2p = rw2 + layer * CHAN * 256 + cidx;
        unsigned long long acc[16];
#pragma unroll
        for (int m = 0; m < 16; m++) acc[m] = 0ull;

#pragma unroll 2
        for (int jb = 0; jb < 64; jb += 8) {
            unsigned long long wp[8];
#pragma unroll
            for (int u = 0; u < 8; u++) {
                unsigned int wi = __float_as_uint(w2p[(jb + u) * 256]);
                asm("mov.b64 %0, {%1, %1};" : "=l"(wp[u]) : "r"(wi));
            }
#pragma unroll
            for (int u = 0; u < 8; u++) {
                const double2* dp = reinterpret_cast<const double2*>(&shH[jb + u][0]);
#pragma unroll
                for (int q = 0; q < 8; q++) {
                    double2 dv = dp[q];
                    acc[2 * q]     = ffma2(__double_as_longlong(dv.x), wp[u], acc[2 * q]);
                    acc[2 * q + 1] = ffma2(__double_as_longlong(dv.y), wp[u], acc[2 * q + 1]);
                }
            }
        }
        float z[32];
#pragma unroll
        for (int m = 0; m < 16; m++) {
            z[2 * m]     = __uint_as_float((unsigned int)(acc[m] & 0xffffffffull)) * shS[2 * m][c];
            z[2 * m + 1] = __uint_as_float((unsigned int)(acc[m] >> 32)) * shS[2 * m + 1][c];
        }

        // scatter-reduce runs of equal dst (warp-uniform control flow)
        const float inv = 1.f / 16.f;
        float* Abase = g_A + (size_t)c * NKC;
        if (L == 0) {
            float s0 = 0.f;
            int cur = shDst[0];
#pragma unroll
            for (int i = 0; i < 32; i++) {
                int d = shDst[i];
                if (d != cur) {
                    atomicAdd(&Abase[(size_t)cur * CHAN * NKC + 0], s0 * inv);
                    s0 = 0.f; cur = d;
                }
                s0 += z[i];
            }
            atomicAdd(&Abase[(size_t)cur * CHAN * NKC + 0], s0 * inv);
        } else if (L == 1) {
            float s1[3] = {0.f, 0.f, 0.f};
            int cur = shDst[0];
#pragma unroll
            for (int i = 0; i < 32; i++) {
                int d = shDst[i];
                if (d != cur) {
#pragma unroll
                    for (int k = 0; k < 3; k++) {
                        atomicAdd(&Abase[(size_t)cur * CHAN * NKC + 1 + k], s1[k] * inv);
                        s1[k] = 0.f;
                    }
                    cur = d;
                }
                float zv = z[i];
#pragma unroll
                for (int k = 0; k < 3; k++) s1[k] += zv * shYc[i][k];
            }
#pragma unroll
            for (int k = 0; k < 3; k++)
                atomicAdd(&Abase[(size_t)cur * CHAN * NKC + 1 + k], s1[k] * inv);
        } else {
            float s2[6];
#pragma unroll
            for (int k = 0; k < 6; k++) s2[k] = 0.f;
            int cur = shDst[0];
#pragma unroll
            for (int i = 0; i < 32; i++) {
                int d = shDst[i];
                if (d != cur) {
#pragma unroll
                    for (int k = 0; k < 6; k++) {
                        atomicAdd(&Abase[(size_t)cur * CHAN * NKC + 4 + k], s2[k] * inv);
                        s2[k] = 0.f;
                    }
                    cur = d;
                }
                float zv = z[i];
#pragma unroll
                for (int k = 0; k < 6; k++) s2[k] += zv * shYc[i][3 + k];
            }
#pragma unroll
            for (int k = 0; k < 6; k++)
                atomicAdd(&Abase[(size_t)cur * CHAN * NKC + 4 + k], s2[k] * inv);
        }
    }
}

// self-contraction + output (compact rank-2); re-zeros A slice for next layer
__global__ void k_update(const float* __restrict__ Wmix, const float* __restrict__ Wsc,
                         const int* __restrict__ spec, float* __restrict__ out,
                         int layer, int N) {
    __shared__ float sA[CHAN * NKC];
    int n = blockIdx.x;
    int d = threadIdx.x;
    for (int i = d; i < CHAN * NKC; i += CHAN) sA[i] = g_A[n * CHAN * NKC + i];
    __syncthreads();
    for (int i = d; i < CHAN * NKC; i += CHAN) g_A[n * CHAN * NKC + i] = 0.f;

    const float* h0in = (layer == 0) ? g_h0a : g_h0b;
    float* h0out = (layer == 0) ? g_h0b : g_h0a;

    float A0d = sA[d * NKC];
    float A1d[3], A2c[6];
#pragma unroll
    for (int k = 0; k < 3; k++) A1d[k] = sA[d * NKC + 1 + k];
#pragma unroll
    for (int k = 0; k < 6; k++) A2c[k] = sA[d * NKC + 4 + k];

    const float* Wm = Wmix + layer * 3 * CHAN * CHAN;
    float mat0 = 0.f;
    float mat1[3] = {0.f, 0.f, 0.f};
    float mat2[6] = {0.f, 0.f, 0.f, 0.f, 0.f, 0.f};
    for (int c = 0; c < CHAN; c++) {
        mat0 += sA[c * NKC] * Wm[c * CHAN + d];
        if (layer == 0) {
            float w1m = Wm[CHAN * CHAN + c * CHAN + d];
#pragma unroll
            for (int k = 0; k < 3; k++) mat1[k] += sA[c * NKC + 1 + k] * w1m;
            float w2m = Wm[2 * CHAN * CHAN + c * CHAN + d];
#pragma unroll
            for (int k = 0; k < 6; k++) mat2[k] += sA[c * NKC + 4 + k] * w2m;
        }
    }
    // |A1|^2 + |A2|^2 (full 9-component norm from compact 6)
    float sq = A1d[0] * A1d[0] + A1d[1] * A1d[1] + A1d[2] * A1d[2]
             + A2c[0] * A2c[0] + A2c[3] * A2c[3] + A2c[5] * A2c[5]
             + 2.f * (A2c[1] * A2c[1] + A2c[2] * A2c[2] + A2c[4] * A2c[4]);

    int sp = spec[n];
    float sc0 = Wsc[layer * 10 * CHAN + sp * CHAN + d] * h0in[n * CHAN + d];
    float o0 = mat0 + sq + sc0;
    out[n * 128 + layer * CHAN + d] = o0;
    h0out[n * CHAN + d] = o0;

    if (layer == 0) {
        // A2 full matrix rows from compact: [xx,xy,xz; xy,yy,yz; xz,yz,zz]
        float m00 = A2c[0], m01 = A2c[1], m02 = A2c[2];
        float m11 = A2c[3], m12 = A2c[4], m22 = A2c[5];
        float v0 = mat1[0] + A0d * A1d[0] + m00 * A1d[0] + m01 * A1d[1] + m02 * A1d[2];
        float v1 = mat1[1] + A0d * A1d[1] + m01 * A1d[0] + m11 * A1d[1] + m12 * A1d[2];
        float v2 = mat1[2] + A0d * A1d[2] + m02 * A1d[0] + m12 * A1d[1] + m22 * A1d[2];
        g_h1[n * 3 * CHAN + 0 * CHAN + d] = v0;
        g_h1[n * 3 * CHAN + 1 * CHAN + d] = v1;
        g_h1[n * 3 * CHAN + 2 * CHAN + d] = v2;
        // compact pairs: (0,0),(0,1),(0,2),(1,1),(1,2),(2,2)
        g_h2[n * 6 * CHAN + 0 * CHAN + d] = mat2[0] + A1d[0] * A1d[0] + A0d * m00;
        g_h2[n * 6 * CHAN + 1 * CHAN + d] = mat2[1] + A1d[0] * A1d[1] + A0d * m01;
        g_h2[n * 6 * CHAN + 2 * CHAN + d] = mat2[2] + A1d[0] * A1d[2] + A0d * m02;
        g_h2[n * 6 * CHAN + 3 * CHAN + d] = mat2[3] + A1d[1] * A1d[1] + A0d * m11;
        g_h2[n * 6 * CHAN + 4 * CHAN + d] = mat2[4] + A1d[1] * A1d[2] + A0d * m12;
        g_h2[n * 6 * CHAN + 5 * CHAN + d] = mat2[5] + A1d[2] * A1d[2] + A0d * m22;
    }
}

// ---------------- launch -----------------------------------------------------
extern "C" void kernel_launch(void* const* d_in, const int* in_sizes, int n_in,
                              void* d_out, int out_size) {
    const float* edge_vec = (const float*)d_in[0];
    const int*   species  = (const int*)d_in[1];
    const int*   eidx     = (const int*)d_in[2];
    const float* W_emb    = (const float*)d_in[3];
    const float* rw1      = (const float*)d_in[4];
    const float* rw2      = (const float*)d_in[5];
    const float* Wg       = (const float*)d_in[6];
    const float* Wsc      = (const float*)d_in[7];
    const float* Wmix     = (const float*)d_in[8];
    float* out = (float*)d_out;

    int E = in_sizes[0] / 3;
    int N = in_sizes[1];
    int GB_E = (E + 255) / 256;
    int GB_N = (N + 3) / 4;

    k_geomgate<<<GB_E + GB_N, 256>>>(edge_vec, species, W_emb, Wg, E, N, GB_E, GB_N); // 0
    k_scanhist<<<1, 1024>>>(eidx, E, N);                                              // 1
    k_place<<<GB_E, 256>>>(eidx, E);                                                  // 2

    k_edge<<<E / 32, 384>>>(rw1, rw2, eidx, E, 0);                                    // 3 <- profiled
    k_update<<<N, CHAN>>>(Wmix, Wsc, species, out, 0, N);                             // 4
    k_gate<<<GB_N, 256>>>(Wg, N);                                                     // 5
    k_edge<<<E / 32, 384>>>(rw1, rw2, eidx, E, 1);                                    // 6
    k_update<<<N, CHAN>>>(Wmix, Wsc, species, out, 1, N);                             // 7
}

// round 9
// speedup vs baseline: 2.8794x; 1.1042x over previous
#include <cuda_runtime.h>
#include <math.h>

// Dataset is fixed: N=4000, E=64000, C=64
#define NMAX 4000
#define EMAX 64000
#define CHAN 64
#define NB 8
#define NY 9            // compact harmonics: ux,uy,uz,xx,xy,xz,yy,yz,zz
#define NKC 10          // compact A components: 1 + 3 + 6

// ---------------- scratch (static device globals) ----------------------------
__device__ float g_ef[EMAX * NB];            // radial basis per edge (edge order)
__device__ float g_Y[EMAX * NY];             // compact harmonics (edge order)
__device__ float g_A[NMAX * CHAN * NKC];     // node features A[n][c][k] compact
__device__ float g_h0a[NMAX * CHAN];
__device__ float g_h0b[NMAX * CHAN];
__device__ float g_h1[NMAX * 3 * CHAN];      // layout [n][k][c]
__device__ float g_h2[NMAX * 6 * CHAN];      // compact symmetric, layout [n][k][c]
__device__ float g_s[NMAX * CHAN];           // gate scalars
__device__ int   g_cur[NMAX];                // atomic cursors
__device__ int   g_eid[EMAX];                // sorted position -> original edge
__device__ int   g_dstp[EMAX];               // sorted position -> dst node

// packed f32x2 FMA (Blackwell)
__device__ __forceinline__ unsigned long long ffma2(unsigned long long a,
                                                    unsigned long long b,
                                                    unsigned long long c) {
    unsigned long long d;
    asm("fma.rn.f32x2 %0, %1, %2, %3;" : "=l"(d) : "l"(a), "l"(b), "l"(c));
    return d;
}

// ---------------- fused setup: geometry | h0-init + gate0 + zero A -----------
__global__ void k_geomgate(const float* __restrict__ ev, const int* __restrict__ spec,
                           const float* __restrict__ Wemb, const float* __restrict__ Wg,
                           int E, int N, int GB_E, int GB_N) {
    if ((int)blockIdx.x < GB_E) {
        int e = blockIdx.x * blockDim.x + threadIdx.x;
        if (e >= E) return;
        float vx = ev[3 * e], vy = ev[3 * e + 1], vz = ev[3 * e + 2];
        float r = sqrtf(vx * vx + vy * vy + vz * vz);
        float inv = 1.f / r;
        float ux = vx * inv, uy = vy * inv, uz = vz * inv;
        float x = r * (1.f / 6.f);
        float fc = 0.f;
        if (x < 1.f) {
            float x2 = x * x;
            float x5 = x2 * x2 * x;
            fc = 1.f - 21.f * x5 + 35.f * x5 * x - 15.f * x5 * x2;
        }
        float pref = sqrtf(2.f / 6.f) * inv * fc;
        const float PI = 3.14159265358979323846f;
        float a = PI * x;
        float s1, c1;
        __sincosf(a, &s1, &c1);
        float twoc = 2.f * c1;
        float skm = 0.f, sk = s1;
        float* efp = g_ef + e * NB;
#pragma unroll
        for (int n = 0; n < NB; n++) {
            efp[n] = pref * sk;
            float nx = twoc * sk - skm;
            skm = sk; sk = nx;
        }
        float* Y = g_Y + e * NY;
        Y[0] = ux; Y[1] = uy; Y[2] = uz;
        Y[3] = ux * ux; Y[4] = ux * uy; Y[5] = ux * uz;
        Y[6] = uy * uy; Y[7] = uy * uz; Y[8] = uz * uz;
    } else {
        __shared__ float sh0[4][CHAN];
        int nb = blockIdx.x - GB_E;
        int g = threadIdx.x >> 6;
        int c = threadIdx.x & 63;
        int n = nb * 4 + g;
        int stride = GB_N * 256;
        for (int i = nb * 256 + threadIdx.x; i < N * CHAN * NKC; i += stride) g_A[i] = 0.f;
        if (n >= N) return;
        float h0 = Wemb[spec[n] * CHAN + c];
        g_h0a[n * CHAN + c] = h0;
        sh0[g][c] = h0;
        __syncthreads();
        float acc = 0.f;
#pragma unroll 8
        for (int d = 0; d < CHAN; d++) acc += sh0[g][d] * Wg[d * CHAN + c];
        g_s[n * CHAN + c] = acc;
    }
}

// ---------------- histogram + exclusive scan (one block) ---------------------
__global__ void k_scanhist(const int* __restrict__ eidx, int E, int N) {
    __shared__ int hist[NMAX];
    __shared__ int sh[1024];
    __shared__ int carry_s;
    int t = threadIdx.x;
    for (int i = t; i < N; i += 1024) hist[i] = 0;
    if (t == 0) carry_s = 0;
    __syncthreads();
    for (int e = t; e < E; e += 1024) atomicAdd(&hist[eidx[E + e]], 1);
    __syncthreads();
    int ntile = (N + 1023) / 1024;
    for (int tile = 0; tile < ntile; tile++) {
        int i = tile * 1024 + t;
        int v = (i < N) ? hist[i] : 0;
        sh[t] = v;
        __syncthreads();
        for (int o = 1; o < 1024; o <<= 1) {
            int add = (t >= o) ? sh[t - o] : 0;
            __syncthreads();
            sh[t] += add;
            __syncthreads();
        }
        int incl = sh[t];
        int carry = carry_s;
        if (i < N) g_cur[i] = carry + incl - v;
        __syncthreads();
        if (t == 1023) carry_s = carry + incl;
        __syncthreads();
    }
}

__global__ void k_place(const int* __restrict__ eidx, int E) {
    int e = blockIdx.x * blockDim.x + threadIdx.x;
    if (e >= E) return;
    int d = eidx[E + e];
    int pos = atomicAdd(&g_cur[d], 1);
    g_eid[pos] = e;
    g_dstp[pos] = d;
}

// ---------------- per-layer kernels ------------------------------------------
__global__ void k_gate(const float* __restrict__ Wg, int N) {
    __shared__ float sh0[4][CHAN];
    int g = threadIdx.x >> 6;
    int c = threadIdx.x & 63;
    int n = blockIdx.x * 4 + g;
    if (n >= N) return;
    sh0[g][c] = g_h0b[n * CHAN + c];
    __syncthreads();
    const float* W = Wg + CHAN * CHAN;
    float acc = 0.f;
#pragma unroll 8
    for (int d = 0; d < CHAN; d++) acc += sh0[g][d] * W[d * CHAN + c];
    g_s[n * CHAN + c] = acc;
}

// fused edge kernel: radial MLP + gate + message + compact scatter-reduce.
// Block = 32 consecutive sorted positions, 384 threads.
// Phase 3: thread = (column cidx, edge-half hf); 8 packed accs (16 edges).
__global__ void __launch_bounds__(384) k_edge(
        const float* __restrict__ rw1, const float* __restrict__ rw2,
        const int* __restrict__ eidx, int E, int layer) {
    __shared__ __align__(16) float shH[64][36];  // hidden [j][edge]
    __shared__ float shS[32][64];                // s_e [edge][c]
    __shared__ float shYc[32][NY];               // compact harmonics per edge
    __shared__ float shEf[32][NB];               // staged radial basis
    __shared__ int   shEid[32];
    __shared__ int   shDst[32];
    int p0 = blockIdx.x * 32;
    int tid = threadIdx.x;
    const float* W1 = rw1 + layer * NB * CHAN;

    if (tid < 32) {
        shEid[tid] = g_eid[p0 + tid];
        shDst[tid] = g_dstp[p0 + tid];
    }
    __syncthreads();

    // stage ef + Y into smem
    if (tid < 256) {
        int el = tid >> 3, i = tid & 7;
        shEf[el][i] = g_ef[shEid[el] * NB + i];
    }
    for (int i = tid; i < 32 * NY; i += 384) {
        int el = i / NY, k = i % NY;
        shYc[el][k] = g_Y[shEid[el] * NY + k];
    }
    __syncthreads();

    // phases 1+2 over (el, c)
    for (int idx = tid; idx < 32 * CHAN; idx += 384) {
        int c = idx & 63;
        int el = idx >> 6;
        int e = shEid[el];
        float h = 0.f;
#pragma unroll
        for (int i = 0; i < NB; i++) h += shEf[el][i] * W1[i * CHAN + c];
        h = h * (1.f / (1.f + __expf(-h)));   // silu
        shH[c][el] = h;

        int src = eidx[e];
        float se = g_s[src * CHAN + c];
        if (layer > 0) {
            const float* y = shYc[el];
            const float* h1 = g_h1 + src * 3 * CHAN + c;
            se += h1[0] * y[0] + h1[CHAN] * y[1] + h1[2 * CHAN] * y[2];
            const float* h2 = g_h2 + src * 6 * CHAN + c;
            se += h2[0] * y[3] + 2.f * h2[CHAN] * y[4] + 2.f * h2[2 * CHAN] * y[5]
                + h2[3 * CHAN] * y[6] + 2.f * h2[4 * CHAN] * y[7] + h2[5 * CHAN] * y[8];
        }
        shS[el][c] = se;
    }
    __syncthreads();

    // phase 3: all 384 threads; thread -> (cidx 0..191, hf 0..1)
    {
        int cidx = tid % 192;
        int hf = tid / 192;
        int c = cidx & 63;
        int L = cidx >> 6;
        int eb0 = hf * 16;
        const float* w2p = rw2 + layer * CHAN * 256 + cidx;
        unsigned long long acc[8];
#pragma unroll
        for (int m = 0; m < 8; m++) acc[m] = 0ull;

#pragma unroll
        for (int jb = 0; jb < 64; jb += 8) {
            unsigned long long wp[8];
#pragma unroll
            for (int u = 0; u < 8; u++) {
                unsigned int wi = __float_as_uint(w2p[(jb + u) * 256]);
                asm("mov.b64 %0, {%1, %1};" : "=l"(wp[u]) : "r"(wi));
            }
#pragma unroll
            for (int u = 0; u < 8; u++) {
                const double2* dp = reinterpret_cast<const double2*>(&shH[jb + u][eb0]);
#pragma unroll
                for (int q = 0; q < 4; q++) {
                    double2 dv = dp[q];
                    acc[2 * q]     = ffma2(__double_as_longlong(dv.x), wp[u], acc[2 * q]);
                    acc[2 * q + 1] = ffma2(__double_as_longlong(dv.y), wp[u], acc[2 * q + 1]);
                }
            }
        }
        float z[16];
#pragma unroll
        for (int m = 0; m < 8; m++) {
            int ea = eb0 + 2 * m;
            z[2 * m]     = __uint_as_float((unsigned int)(acc[m] & 0xffffffffull)) * shS[ea][c];
            z[2 * m + 1] = __uint_as_float((unsigned int)(acc[m] >> 32)) * shS[ea + 1][c];
        }

        // scatter-reduce runs of equal dst within this 16-edge half
        const float inv = 1.f / 16.f;
        float* Abase = g_A + (size_t)c * NKC;
        if (L == 0) {
            float s0 = 0.f;
            int cur = shDst[eb0];
#pragma unroll
            for (int i = 0; i < 16; i++) {
                int el = eb0 + i;
                int d = shDst[el];
                if (d != cur) {
                    atomicAdd(&Abase[(size_t)cur * CHAN * NKC + 0], s0 * inv);
                    s0 = 0.f; cur = d;
                }
                s0 += z[i];
            }
            atomicAdd(&Abase[(size_t)cur * CHAN * NKC + 0], s0 * inv);
        } else if (L == 1) {
            float s1[3] = {0.f, 0.f, 0.f};
            int cur = shDst[eb0];
#pragma unroll
            for (int i = 0; i < 16; i++) {
                int el = eb0 + i;
                int d = shDst[el];
                if (d != cur) {
#pragma unroll
                    for (int k = 0; k < 3; k++) {
                        atomicAdd(&Abase[(size_t)cur * CHAN * NKC + 1 + k], s1[k] * inv);
                        s1[k] = 0.f;
                    }
                    cur = d;
                }
                float zv = z[i];
#pragma unroll
                for (int k = 0; k < 3; k++) s1[k] += zv * shYc[el][k];
            }
#pragma unroll
            for (int k = 0; k < 3; k++)
                atomicAdd(&Abase[(size_t)cur * CHAN * NKC + 1 + k], s1[k] * inv);
        } else {
            float s2[6];
#pragma unroll
            for (int k = 0; k < 6; k++) s2[k] = 0.f;
            int cur = shDst[eb0];
#pragma unroll
            for (int i = 0; i < 16; i++) {
                int el = eb0 + i;
                int d = shDst[el];
                if (d != cur) {
#pragma unroll
                    for (int k = 0; k < 6; k++) {
                        atomicAdd(&Abase[(size_t)cur * CHAN * NKC + 4 + k], s2[k] * inv);
                        s2[k] = 0.f;
                    }
                    cur = d;
                }
                float zv = z[i];
#pragma unroll
                for (int k = 0; k < 6; k++) s2[k] += zv * shYc[el][3 + k];
            }
#pragma unroll
            for (int k = 0; k < 6; k++)
                atomicAdd(&Abase[(size_t)cur * CHAN * NKC + 4 + k], s2[k] * inv);
        }
    }
}

// self-contraction + output (compact rank-2); re-zeros A slice for next layer
__global__ void k_update(const float* __restrict__ Wmix, const float* __restrict__ Wsc,
                         const int* __restrict__ spec, float* __restrict__ out,
                         int layer, int N) {
    __shared__ float sA[CHAN * NKC];
    int n = blockIdx.x;
    int d = threadIdx.x;
    for (int i = d; i < CHAN * NKC; i += CHAN) sA[i] = g_A[n * CHAN * NKC + i];
    __syncthreads();
    for (int i = d; i < CHAN * NKC; i += CHAN) g_A[n * CHAN * NKC + i] = 0.f;

    const float* h0in = (layer == 0) ? g_h0a : g_h0b;
    float* h0out = (layer == 0) ? g_h0b : g_h0a;

    float A0d = sA[d * NKC];
    float A1d[3], A2c[6];
#pragma unroll
    for (int k = 0; k < 3; k++) A1d[k] = sA[d * NKC + 1 + k];
#pragma unroll
    for (int k = 0; k < 6; k++) A2c[k] = sA[d * NKC + 4 + k];

    const float* Wm = Wmix + layer * 3 * CHAN * CHAN;
    float mat0 = 0.f;
    float mat1[3] = {0.f, 0.f, 0.f};
    float mat2[6] = {0.f, 0.f, 0.f, 0.f, 0.f, 0.f};
    for (int c = 0; c < CHAN; c++) {
        mat0 += sA[c * NKC] * Wm[c * CHAN + d];
        if (layer == 0) {
            float w1m = Wm[CHAN * CHAN + c * CHAN + d];
#pragma unroll
            for (int k = 0; k < 3; k++) mat1[k] += sA[c * NKC + 1 + k] * w1m;
            float w2m = Wm[2 * CHAN * CHAN + c * CHAN + d];
#pragma unroll
            for (int k = 0; k < 6; k++) mat2[k] += sA[c * NKC + 4 + k] * w2m;
        }
    }
    // |A1|^2 + |A2|^2 (full 9-component norm from compact 6)
    float sq = A1d[0] * A1d[0] + A1d[1] * A1d[1] + A1d[2] * A1d[2]
             + A2c[0] * A2c[0] + A2c[3] * A2c[3] + A2c[5] * A2c[5]
             + 2.f * (A2c[1] * A2c[1] + A2c[2] * A2c[2] + A2c[4] * A2c[4]);

    int sp = spec[n];
    float sc0 = Wsc[layer * 10 * CHAN + sp * CHAN + d] * h0in[n * CHAN + d];
    float o0 = mat0 + sq + sc0;
    out[n * 128 + layer * CHAN + d] = o0;
    h0out[n * CHAN + d] = o0;

    if (layer == 0) {
        float m00 = A2c[0], m01 = A2c[1], m02 = A2c[2];
        float m11 = A2c[3], m12 = A2c[4], m22 = A2c[5];
        float v0 = mat1[0] + A0d * A1d[0] + m00 * A1d[0] + m01 * A1d[1] + m02 * A1d[2];
        float v1 = mat1[1] + A0d * A1d[1] + m01 * A1d[0] + m11 * A1d[1] + m12 * A1d[2];
        float v2 = mat1[2] + A0d * A1d[2] + m02 * A1d[0] + m12 * A1d[1] + m22 * A1d[2];
        g_h1[n * 3 * CHAN + 0 * CHAN + d] = v0;
        g_h1[n * 3 * CHAN + 1 * CHAN + d] = v1;
        g_h1[n * 3 * CHAN + 2 * CHAN + d] = v2;
        g_h2[n * 6 * CHAN + 0 * CHAN + d] = mat2[0] + A1d[0] * A1d[0] + A0d * m00;
        g_h2[n * 6 * CHAN + 1 * CHAN + d] = mat2[1] + A1d[0] * A1d[1] + A0d * m01;
        g_h2[n * 6 * CHAN + 2 * CHAN + d] = mat2[2] + A1d[0] * A1d[2] + A0d * m02;
        g_h2[n * 6 * CHAN + 3 * CHAN + d] = mat2[3] + A1d[1] * A1d[1] + A0d * m11;
        g_h2[n * 6 * CHAN + 4 * CHAN + d] = mat2[4] + A1d[1] * A1d[2] + A0d * m12;
        g_h2[n * 6 * CHAN + 5 * CHAN + d] = mat2[5] + A1d[2] * A1d[2] + A0d * m22;
    }
}

// ---------------- launch -----------------------------------------------------
extern "C" void kernel_launch(void* const* d_in, const int* in_sizes, int n_in,
                              void* d_out, int out_size) {
    const float* edge_vec = (const float*)d_in[0];
    const int*   species  = (const int*)d_in[1];
    const int*   eidx     = (const int*)d_in[2];
    const float* W_emb    = (const float*)d_in[3];
    const float* rw1      = (const float*)d_in[4];
    const float* rw2      = (const float*)d_in[5];
    const float* Wg       = (const float*)d_in[6];
    const float* Wsc      = (const float*)d_in[7];
    const float* Wmix     = (const float*)d_in[8];
    float* out = (float*)d_out;

    int E = in_sizes[0] / 3;
    int N = in_sizes[1];
    int GB_E = (E + 255) / 256;
    int GB_N = (N + 3) / 4;

    k_geomgate<<<GB_E + GB_N, 256>>>(edge_vec, species, W_emb, Wg, E, N, GB_E, GB_N); // 0
    k_scanhist<<<1, 1024>>>(eidx, E, N);                                              // 1
    k_place<<<GB_E, 256>>>(eidx, E);                                                  // 2

    k_edge<<<E / 32, 384>>>(rw1, rw2, eidx, E, 0);                                    // 3 <- profiled
    k_update<<<N, CHAN>>>(Wmix, Wsc, species, out, 0, N);                             // 4
    k_gate<<<GB_N, 256>>>(Wg, N);                                                     // 5
    k_edge<<<E / 32, 384>>>(rw1, rw2, eidx, E, 1);                                    // 6
    k_update<<<N, CHAN>>>(Wmix, Wsc, species, out, 1, N);                             // 7
}

// round 11
// speedup vs baseline: 2.9556x; 1.0265x over previous
#include <cuda_runtime.h>
#include <math.h>

// Dataset is fixed: N=4000, E=64000, C=64
#define NMAX 4000
#define EMAX 64000
#define CHAN 64
#define NB 8
#define NY 9            // compact harmonics: ux,uy,uz,xx,xy,xz,yy,yz,zz
#define NKC 10          // compact A components: 1 + 3 + 6

// ---------------- scratch (static device globals) ----------------------------
__device__ float g_ef[EMAX * NB];            // radial basis per edge (edge order)
__device__ float g_Y[EMAX * NY];             // compact harmonics (edge order)
__device__ float g_A[NMAX * CHAN * NKC];     // node features A[n][c][k] compact
__device__ float g_h0a[NMAX * CHAN];
__device__ float g_h0b[NMAX * CHAN];
__device__ float g_h1[NMAX * 3 * CHAN];      // layout [n][k][c]
__device__ float g_h2[NMAX * 6 * CHAN];      // compact symmetric, layout [n][k][c]
__device__ float g_s[NMAX * CHAN];           // gate scalars
__device__ int   g_cnt[NMAX];                // histogram (self-restoring to 0)
__device__ int   g_cur[NMAX];                // atomic cursors
__device__ int   g_eid[EMAX];                // sorted position -> original edge
__device__ int   g_dstp[EMAX];               // sorted position -> dst node

// packed f32x2 FMA (Blackwell)
__device__ __forceinline__ unsigned long long ffma2(unsigned long long a,
                                                    unsigned long long b,
                                                    unsigned long long c) {
    unsigned long long d;
    asm("fma.rn.f32x2 %0, %1, %2, %3;" : "=l"(d) : "l"(a), "l"(b), "l"(c));
    return d;
}

// ---------------- fused setup: geometry + dst count | h0 + gate0 + zero A ----
__global__ void k_geomgate(const float* __restrict__ ev, const int* __restrict__ spec,
                           const float* __restrict__ Wemb, const float* __restrict__ Wg,
                           const int* __restrict__ eidx,
                           int E, int N, int GB_E, int GB_N) {
    if ((int)blockIdx.x < GB_E) {
        int e = blockIdx.x * blockDim.x + threadIdx.x;
        if (e >= E) return;
        float vx = ev[3 * e], vy = ev[3 * e + 1], vz = ev[3 * e + 2];
        float r = sqrtf(vx * vx + vy * vy + vz * vz);
        float inv = 1.f / r;
        float ux = vx * inv, uy = vy * inv, uz = vz * inv;
        float x = r * (1.f / 6.f);
        float fc = 0.f;
        if (x < 1.f) {
            float x2 = x * x;
            float x5 = x2 * x2 * x;
            fc = 1.f - 21.f * x5 + 35.f * x5 * x - 15.f * x5 * x2;
        }
        float pref = sqrtf(2.f / 6.f) * inv * fc;
        const float PI = 3.14159265358979323846f;
        float a = PI * x;
        float s1, c1;
        __sincosf(a, &s1, &c1);
        float twoc = 2.f * c1;
        float skm = 0.f, sk = s1;
        float* efp = g_ef + e * NB;
#pragma unroll
        for (int n = 0; n < NB; n++) {
            efp[n] = pref * sk;
            float nx = twoc * sk - skm;
            skm = sk; sk = nx;
        }
        float* Y = g_Y + e * NY;
        Y[0] = ux; Y[1] = uy; Y[2] = uz;
        Y[3] = ux * ux; Y[4] = ux * uy; Y[5] = ux * uz;
        Y[6] = uy * uy; Y[7] = uy * uz; Y[8] = uz * uz;
        // dst histogram (g_cnt zero at entry: module-load zero on first call,
        // restored to zero by k_scan on every call)
        atomicAdd(&g_cnt[eidx[E + e]], 1);
    } else {
        __shared__ float sh0[4][CHAN];
        int nb = blockIdx.x - GB_E;
        int g = threadIdx.x >> 6;
        int c = threadIdx.x & 63;
        int n = nb * 4 + g;
        int stride = GB_N * 256;
        for (int i = nb * 256 + threadIdx.x; i < N * CHAN * NKC; i += stride) g_A[i] = 0.f;
        if (n >= N) return;
        float h0 = Wemb[spec[n] * CHAN + c];
        g_h0a[n * CHAN + c] = h0;
        sh0[g][c] = h0;
        __syncthreads();
        float acc = 0.f;
#pragma unroll 8
        for (int d = 0; d < CHAN; d++) acc += sh0[g][d] * Wg[d * CHAN + c];
        g_s[n * CHAN + c] = acc;
    }
}

// ---------------- exclusive scan of g_cnt -> g_cur; self-restore g_cnt=0 -----
__global__ void k_scan(int N) {
    __shared__ int sh[1024];
    __shared__ int carry_s;
    int t = threadIdx.x;
    if (t == 0) carry_s = 0;
    __syncthreads();
    int ntile = (N + 1023) / 1024;
    for (int tile = 0; tile < ntile; tile++) {
        int i = tile * 1024 + t;
        int v = (i < N) ? g_cnt[i] : 0;
        sh[t] = v;
        __syncthreads();
        for (int o = 1; o < 1024; o <<= 1) {
            int add = (t >= o) ? sh[t - o] : 0;
            __syncthreads();
            sh[t] += add;
            __syncthreads();
        }
        int incl = sh[t];
        int carry = carry_s;
        if (i < N) {
            g_cur[i] = carry + incl - v;   // exclusive prefix
            g_cnt[i] = 0;                  // restore for next call
        }
        __syncthreads();
        if (t == 1023) carry_s = carry + incl;
        __syncthreads();
    }
}

__global__ void k_place(const int* __restrict__ eidx, int E) {
    int e = blockIdx.x * blockDim.x + threadIdx.x;
    if (e >= E) return;
    int d = eidx[E + e];
    int pos = atomicAdd(&g_cur[d], 1);
    g_eid[pos] = e;
    g_dstp[pos] = d;
}

// ---------------- per-layer kernels ------------------------------------------
__global__ void k_gate(const float* __restrict__ Wg, int N) {
    __shared__ float sh0[4][CHAN];
    int g = threadIdx.x >> 6;
    int c = threadIdx.x & 63;
    int n = blockIdx.x * 4 + g;
    if (n >= N) return;
    sh0[g][c] = g_h0b[n * CHAN + c];
    __syncthreads();
    const float* W = Wg + CHAN * CHAN;
    float acc = 0.f;
#pragma unroll 8
    for (int d = 0; d < CHAN; d++) acc += sh0[g][d] * W[d * CHAN + c];
    g_s[n * CHAN + c] = acc;
}

// fused edge kernel. Block = 32 sorted positions, 384 threads.
// Phase 3: thread = (column-pair p: cols 2p,2p+1; edge-octet g: 8 edges).
// Per j: 2 LDS.128 (8 edges, reused for both columns) + 1 LDG.64 (2 weights).
__global__ void __launch_bounds__(384, 3) k_edge(
        const float* __restrict__ rw1, const float* __restrict__ rw2,
        const int* __restrict__ eidx, int E, int layer) {
    __shared__ __align__(16) float shH[64][36];  // hidden [j][edge]
    __shared__ float shS[32][64];                // s_e [edge][c]
    __shared__ float shYc[32][NY];               // compact harmonics per edge
    __shared__ float shEf[32][NB];               // staged radial basis
    __shared__ int   shEid[32];
    __shared__ int   shDst[32];
    int p0 = blockIdx.x * 32;
    int tid = threadIdx.x;
    const float* W1 = rw1 + layer * NB * CHAN;

    if (tid < 32) {
        shEid[tid] = g_eid[p0 + tid];
        shDst[tid] = g_dstp[p0 + tid];
    }
    __syncthreads();

    // stage ef + Y into smem
    if (tid < 256) {
        int el = tid >> 3, i = tid & 7;
        shEf[el][i] = g_ef[shEid[el] * NB + i];
    }
    for (int i = tid; i < 32 * NY; i += 384) {
        int el = i / NY, k = i % NY;
        shYc[el][k] = g_Y[shEid[el] * NY + k];
    }
    __syncthreads();

    // phases 1+2 over (el, c)
    for (int idx = tid; idx < 32 * CHAN; idx += 384) {
        int c = idx & 63;
        int el = idx >> 6;
        int e = shEid[el];
        float h = 0.f;
#pragma unroll
        for (int i = 0; i < NB; i++) h += shEf[el][i] * W1[i * CHAN + c];
        h = h * (1.f / (1.f + __expf(-h)));   // silu
        shH[c][el] = h;

        int src = eidx[e];
        float se = g_s[src * CHAN + c];
        if (layer > 0) {
            const float* y = shYc[el];
            const float* h1 = g_h1 + src * 3 * CHAN + c;
            se += h1[0] * y[0] + h1[CHAN] * y[1] + h1[2 * CHAN] * y[2];
            const float* h2 = g_h2 + src * 6 * CHAN + c;
            se += h2[0] * y[3] + 2.f * h2[CHAN] * y[4] + 2.f * h2[2 * CHAN] * y[5]
                + h2[3 * CHAN] * y[6] + 2.f * h2[4 * CHAN] * y[7] + h2[5 * CHAN] * y[8];
        }
        shS[el][c] = se;
    }
    __syncthreads();

    // phase 3
    {
        int p = tid % 96;           // column pair: cidx = 2p, 2p+1
        int g = tid / 96;           // edge octet
        int eb0 = g * 8;
        int c0 = (2 * p) & 63;
        int c1 = c0 + 1;
        int L = p >> 5;             // 0,1,2 (warp-uniform)
        const float* w2base = rw2 + layer * CHAN * 256 + 2 * p;

        unsigned long long acc[2][4];
#pragma unroll
        for (int m = 0; m < 4; m++) { acc[0][m] = 0ull; acc[1][m] = 0ull; }

#pragma unroll
        for (int jb = 0; jb < 64; jb += 4) {
            float2 wv[4];
#pragma unroll
            for (int u = 0; u < 4; u++)
                wv[u] = *(const float2*)&w2base[(jb + u) * 256];
#pragma unroll
            for (int u = 0; u < 4; u++) {
                unsigned long long wx, wy;
                asm("mov.b64 %0, {%1, %1};" : "=l"(wx) : "r"(__float_as_uint(wv[u].x)));
                asm("mov.b64 %0, {%1, %1};" : "=l"(wy) : "r"(__float_as_uint(wv[u].y)));
                const double2* dp = (const double2*)&shH[jb + u][eb0];
                double2 d0 = dp[0], d1 = dp[1];
                unsigned long long e01 = __double_as_longlong(d0.x);
                unsigned long long e23 = __double_as_longlong(d0.y);
                unsigned long long e45 = __double_as_longlong(d1.x);
                unsigned long long e67 = __double_as_longlong(d1.y);
                acc[0][0] = ffma2(e01, wx, acc[0][0]);
                acc[0][1] = ffma2(e23, wx, acc[0][1]);
                acc[0][2] = ffma2(e45, wx, acc[0][2]);
                acc[0][3] = ffma2(e67, wx, acc[0][3]);
                acc[1][0] = ffma2(e01, wy, acc[1][0]);
                acc[1][1] = ffma2(e23, wy, acc[1][1]);
                acc[1][2] = ffma2(e45, wy, acc[1][2]);
                acc[1][3] = ffma2(e67, wy, acc[1][3]);
            }
        }
        // unpack messages for both columns
        float z0[8], z1[8];
#pragma unroll
        for (int m = 0; m < 4; m++) {
            int ea = eb0 + 2 * m, eb = ea + 1;
            z0[2 * m]     = __uint_as_float((unsigned)(acc[0][m] & 0xffffffffull)) * shS[ea][c0];
            z0[2 * m + 1] = __uint_as_float((unsigned)(acc[0][m] >> 32)) * shS[eb][c0];
            z1[2 * m]     = __uint_as_float((unsigned)(acc[1][m] & 0xffffffffull)) * shS[ea][c1];
            z1[2 * m + 1] = __uint_as_float((unsigned)(acc[1][m] >> 32)) * shS[eb][c1];
        }

        // scatter-reduce runs of equal dst over the 8-edge octet, both columns
        const float inv = 1.f / 16.f;
        float* A0 = g_A + (size_t)c0 * NKC;
        float* A1 = g_A + (size_t)c1 * NKC;
        if (L == 0) {
            float s0 = 0.f, s1 = 0.f;
            int cur = shDst[eb0];
#pragma unroll
            for (int i = 0; i < 8; i++) {
                int d = shDst[eb0 + i];
                if (d != cur) {
                    size_t b = (size_t)cur * CHAN * NKC;
                    atomicAdd(&A0[b], s0 * inv);
                    atomicAdd(&A1[b], s1 * inv);
                    s0 = 0.f; s1 = 0.f; cur = d;
                }
                s0 += z0[i]; s1 += z1[i];
            }
            size_t b = (size_t)cur * CHAN * NKC;
            atomicAdd(&A0[b], s0 * inv);
            atomicAdd(&A1[b], s1 * inv);
        } else if (L == 1) {
            float s0[3] = {0.f, 0.f, 0.f}, s1[3] = {0.f, 0.f, 0.f};
            int cur = shDst[eb0];
#pragma unroll
            for (int i = 0; i < 8; i++) {
                int el = eb0 + i;
                int d = shDst[el];
                if (d != cur) {
                    size_t b = (size_t)cur * CHAN * NKC + 1;
#pragma unroll
                    for (int k = 0; k < 3; k++) {
                        atomicAdd(&A0[b + k], s0[k] * inv);
                        atomicAdd(&A1[b + k], s1[k] * inv);
                        s0[k] = 0.f; s1[k] = 0.f;
                    }
                    cur = d;
                }
                float za = z0[i], zb = z1[i];
#pragma unroll
                for (int k = 0; k < 3; k++) {
                    float yv = shYc[el][k];
                    s0[k] += za * yv; s1[k] += zb * yv;
                }
            }
            size_t b = (size_t)cur * CHAN * NKC + 1;
#pragma unroll
            for (int k = 0; k < 3; k++) {
                atomicAdd(&A0[b + k], s0[k] * inv);
                atomicAdd(&A1[b + k], s1[k] * inv);
            }
        } else {
            float s0[6], s1[6];
#pragma unroll
            for (int k = 0; k < 6; k++) { s0[k] = 0.f; s1[k] = 0.f; }
            int cur = shDst[eb0];
#pragma unroll
            for (int i = 0; i < 8; i++) {
                int el = eb0 + i;
                int d = shDst[el];
                if (d != cur) {
                    size_t b = (size_t)cur * CHAN * NKC + 4;
#pragma unroll
                    for (int k = 0; k < 6; k++) {
                        atomicAdd(&A0[b + k], s0[k] * inv);
                        atomicAdd(&A1[b + k], s1[k] * inv);
                        s0[k] = 0.f; s1[k] = 0.f;
                    }
                    cur = d;
                }
                float za = z0[i], zb = z1[i];
#pragma unroll
                for (int k = 0; k < 6; k++) {
                    float yv = shYc[el][3 + k];
                    s0[k] += za * yv; s1[k] += zb * yv;
                }
            }
            size_t b = (size_t)cur * CHAN * NKC + 4;
#pragma unroll
            for (int k = 0; k < 6; k++) {
                atomicAdd(&A0[b + k], s0[k] * inv);
                atomicAdd(&A1[b + k], s1[k] * inv);
            }
        }
    }
}

// self-contraction + output (compact rank-2); re-zeros A slice for next layer
__global__ void k_update(const float* __restrict__ Wmix, const float* __restrict__ Wsc,
                         const int* __restrict__ spec, float* __restrict__ out,
                         int layer, int N) {
    __shared__ float sA[CHAN * NKC];
    int n = blockIdx.x;
    int d = threadIdx.x;
    for (int i = d; i < CHAN * NKC; i += CHAN) sA[i] = g_A[n * CHAN * NKC + i];
    __syncthreads();
    for (int i = d; i < CHAN * NKC; i += CHAN) g_A[n * CHAN * NKC + i] = 0.f;

    const float* h0in = (layer == 0) ? g_h0a : g_h0b;
    float* h0out = (layer == 0) ? g_h0b : g_h0a;

    float A0d = sA[d * NKC];
    float A1d[3], A2c[6];
#pragma unroll
    for (int k = 0; k < 3; k++) A1d[k] = sA[d * NKC + 1 + k];
#pragma unroll
    for (int k = 0; k < 6; k++) A2c[k] = sA[d * NKC + 4 + k];

    const float* Wm = Wmix + layer * 3 * CHAN * CHAN;
    float mat0 = 0.f;
    float mat1[3] = {0.f, 0.f, 0.f};
    float mat2[6] = {0.f, 0.f, 0.f, 0.f, 0.f, 0.f};
    for (int c = 0; c < CHAN; c++) {
        mat0 += sA[c * NKC] * Wm[c * CHAN + d];
        if (layer == 0) {
            float w1m = Wm[CHAN * CHAN + c * CHAN + d];
#pragma unroll
            for (int k = 0; k < 3; k++) mat1[k] += sA[c * NKC + 1 + k] * w1m;
            float w2m = Wm[2 * CHAN * CHAN + c * CHAN + d];
#pragma unroll
            for (int k = 0; k < 6; k++) mat2[k] += sA[c * NKC + 4 + k] * w2m;
        }
    }
    float sq = A1d[0] * A1d[0] + A1d[1] * A1d[1] + A1d[2] * A1d[2]
             + A2c[0] * A2c[0] + A2c[3] * A2c[3] + A2c[5] * A2c[5]
             + 2.f * (A2c[1] * A2c[1] + A2c[2] * A2c[2] + A2c[4] * A2c[4]);

    int sp = spec[n];
    float sc0 = Wsc[layer * 10 * CHAN + sp * CHAN + d] * h0in[n * CHAN + d];
    float o0 = mat0 + sq + sc0;
    out[n * 128 + layer * CHAN + d] = o0;
    h0out[n * CHAN + d] = o0;

    if (layer == 0) {
        float m00 = A2c[0], m01 = A2c[1], m02 = A2c[2];
        float m11 = A2c[3], m12 = A2c[4], m22 = A2c[5];
        float v0 = mat1[0] + A0d * A1d[0] + m00 * A1d[0] + m01 * A1d[1] + m02 * A1d[2];
        float v1 = mat1[1] + A0d * A1d[1] + m01 * A1d[0] + m11 * A1d[1] + m12 * A1d[2];
        float v2 = mat1[2] + A0d * A1d[2] + m02 * A1d[0] + m12 * A1d[1] + m22 * A1d[2];
        g_h1[n * 3 * CHAN + 0 * CHAN + d] = v0;
        g_h1[n * 3 * CHAN + 1 * CHAN + d] = v1;
        g_h1[n * 3 * CHAN + 2 * CHAN + d] = v2;
        g_h2[n * 6 * CHAN + 0 * CHAN + d] = mat2[0] + A1d[0] * A1d[0] + A0d * m00;
        g_h2[n * 6 * CHAN + 1 * CHAN + d] = mat2[1] + A1d[0] * A1d[1] + A0d * m01;
        g_h2[n * 6 * CHAN + 2 * CHAN + d] = mat2[2] + A1d[0] * A1d[2] + A0d * m02;
        g_h2[n * 6 * CHAN + 3 * CHAN + d] = mat2[3] + A1d[1] * A1d[1] + A0d * m11;
        g_h2[n * 6 * CHAN + 4 * CHAN + d] = mat2[4] + A1d[1] * A1d[2] + A0d * m12;
        g_h2[n * 6 * CHAN + 5 * CHAN + d] = mat2[5] + A1d[2] * A1d[2] + A0d * m22;
    }
}

// ---------------- launch -----------------------------------------------------
extern "C" void kernel_launch(void* const* d_in, const int* in_sizes, int n_in,
                              void* d_out, int out_size) {
    const float* edge_vec = (const float*)d_in[0];
    const int*   species  = (const int*)d_in[1];
    const int*   eidx     = (const int*)d_in[2];
    const float* W_emb    = (const float*)d_in[3];
    const float* rw1      = (const float*)d_in[4];
    const float* rw2      = (const float*)d_in[5];
    const float* Wg       = (const float*)d_in[6];
    const float* Wsc      = (const float*)d_in[7];
    const float* Wmix     = (const float*)d_in[8];
    float* out = (float*)d_out;

    int E = in_sizes[0] / 3;
    int N = in_sizes[1];
    int GB_E = (E + 255) / 256;
    int GB_N = (N + 3) / 4;

    k_geomgate<<<GB_E + GB_N, 256>>>(edge_vec, species, W_emb, Wg, eidx,
                                     E, N, GB_E, GB_N);                // 0
    k_scan<<<1, 1024>>>(N);                                            // 1
    k_place<<<GB_E, 256>>>(eidx, E);                                   // 2

    k_edge<<<E / 32, 384>>>(rw1, rw2, eidx, E, 0);                     // 3 <- profiled
    k_update<<<N, CHAN>>>(Wmix, Wsc, species, out, 0, N);              // 4
    k_gate<<<GB_N, 256>>>(Wg, N);                                      // 5
    k_edge<<<E / 32, 384>>>(rw1, rw2, eidx, E, 1);                     // 6
    k_update<<<N, CHAN>>>(Wmix, Wsc, species, out, 1, N);              // 7
}